// round 11
// baseline (speedup 1.0000x reference)
#include <cuda_runtime.h>
#include <stdint.h>
#include <math.h>

// Problem constants
#define BB      4
#define SS      4096
#define DD      768
#define NHH     8
#define DKV     64
#define PROJ    512          // NH*DK = NH*DV
#define NTOK    16384        // B*S
#define CHUNK   128
#define NC      32           // S / CHUNK
#define STATE_SZ 32768       // NH*DK*DV

// ---------------- device scratch (static, no allocation) ----------------
__device__ float g_q   [NTOK * PROJ];
__device__ float g_k0  [SS * PROJ];
__device__ float g_v0  [SS * PROJ];
__device__ float g_g0  [SS * NHH];
__device__ float g_W   [NC * STATE_SZ];
__device__ float g_Fst [NC * STATE_SZ];
__device__ float g_retr[NTOK * PROJ];
__device__ float g_dpow[136];

// ---------------- tensor-core plumbing (legacy mma path; tcgen05 is not
// available: harness builds compute_103 PTX which ptxas rejects for tcgen05) --
#define MMA_TF32(d, a, b)                                                     \
    asm volatile("mma.sync.aligned.m16n8k8.row.col.f32.tf32.tf32.f32 "        \
                 "{%0,%1,%2,%3}, {%4,%5,%6,%7}, {%8,%9}, {%0,%1,%2,%3};"      \
                 : "+f"((d)[0]), "+f"((d)[1]), "+f"((d)[2]), "+f"((d)[3])     \
                 : "r"((a)[0]), "r"((a)[1]), "r"((a)[2]), "r"((a)[3]),        \
                   "r"((b)[0]), "r"((b)[1]))

#define LDSM4(r0, r1, r2, r3, addr)                                           \
    asm volatile("ldmatrix.sync.aligned.m8n8.x4.shared.b16 {%0,%1,%2,%3}, [%4];" \
                 : "=r"(r0), "=r"(r1), "=r"(r2), "=r"(r3) : "r"(addr))

#define CP_ASYNC16(dst, src)                                                  \
    asm volatile("cp.async.cg.shared.global [%0], [%1], 16;" :: "r"(dst), "l"(src))
#define CP_COMMIT() asm volatile("cp.async.commit_group;")
#define CP_WAIT1()  asm volatile("cp.async.wait_group 1;")
#define CP_WAIT0()  asm volatile("cp.async.wait_group 0;")

// ================= projection GEMM body =================
// 128x128 block, BK=32, 256 threads = 8 warps (2x4), warp tile 64x32.
// 3-stage cp.async pipeline, one __syncthreads per K-iter.
// Smem row-major, pitch 36 floats (conflict-free: bank=(4r+c) mod 32).
#define TG_P      36
#define TG_BUFB   (128 * TG_P * 4)             // bytes per stage buffer (18432)
#define TG_SMEM   (6 * TG_BUFB)                // A[3] + B[3] = 110592 bytes

// mode 0: C[r][c] (+Cadd) normal store.  mode 1: gate — write sigmoid of
// cols 0..7 into g_g0[token*NHH+col]; B has only 8 valid rows (bmask=7).
__device__ __forceinline__ void gemm_body(
    const float* __restrict__ A, const float* __restrict__ Bm,
    const float* __restrict__ Cadd, float* __restrict__ C,
    int N, int K, int bx, int by, int bmask, int mode)
{
    extern __shared__ float smg[];
    uint32_t sA = (uint32_t)__cvta_generic_to_shared(smg);
    uint32_t sB = sA + 3 * TG_BUFB;

    int t    = threadIdx.x;
    int warp = t >> 5, lane = t & 31;
    int wm = warp >> 2, wn = warp & 3;     // warp grid 2 x 4
    int g  = lane >> 3, gr = lane & 7;     // ldmatrix groups
    int lr = lane >> 2, lc = lane & 3;     // mma C-fragment decomposition

    int ldr = t & 127, ldc = (t >> 7) * 16;
    const float* gA = A  + (size_t)(by * 128 + ldr) * K + ldc;
    const float* gB = Bm + (size_t)(bx * 128 + (ldr & bmask)) * K + ldc;
    uint32_t dA = sA + (uint32_t)(ldr * TG_P + ldc) * 4;
    uint32_t dB = sB + (uint32_t)(ldr * TG_P + ldc) * 4;

    uint32_t aAddr[4];
#pragma unroll
    for (int mt = 0; mt < 4; mt++)
        aAddr[mt] = sA + (uint32_t)(((wm * 64 + mt * 16 + (g & 1) * 8 + gr) * TG_P
                                     + (g >> 1) * 4) * 4);
    uint32_t bAddr[2];
#pragma unroll
    for (int np = 0; np < 2; np++)
        bAddr[np] = sB + (uint32_t)(((wn * 32 + (2 * np + (g >> 1)) * 8 + gr) * TG_P
                                     + (g & 1) * 4) * 4);

    float acc[4][4][4];
#pragma unroll
    for (int i = 0; i < 4; i++)
#pragma unroll
        for (int j = 0; j < 4; j++)
#pragma unroll
            for (int r = 0; r < 4; r++) acc[i][j][r] = 0.f;

    const int NIT = K >> 5;

    // prologue: stages 0 and 1
#pragma unroll
    for (int i = 0; i < 4; i++) {
        CP_ASYNC16(dA + 16 * i, gA + 4 * i);
        CP_ASYNC16(dB + 16 * i, gB + 4 * i);
    }
    CP_COMMIT();
#pragma unroll
    for (int i = 0; i < 4; i++) {
        CP_ASYNC16(dA + TG_BUFB + 16 * i, gA + 32 + 4 * i);
        CP_ASYNC16(dB + TG_BUFB + 16 * i, gB + 32 + 4 * i);
    }
    CP_COMMIT();

    int st = 0, st2 = 2;
    for (int it = 0; it < NIT; it++) {
        if (it < NIT - 1) CP_WAIT1(); else CP_WAIT0();
        __syncthreads();

        uint32_t oa = (uint32_t)st * TG_BUFB;
#pragma unroll
        for (int ks = 0; ks < 4; ks++) {
            uint32_t af[4][4];
#pragma unroll
            for (int mt = 0; mt < 4; mt++)
                LDSM4(af[mt][0], af[mt][1], af[mt][2], af[mt][3],
                      aAddr[mt] + oa + ks * 32);
            uint32_t bf[4][2];
#pragma unroll
            for (int np = 0; np < 2; np++)
                LDSM4(bf[2 * np][0], bf[2 * np][1], bf[2 * np + 1][0], bf[2 * np + 1][1],
                      bAddr[np] + oa + ks * 32);
#pragma unroll
            for (int mt = 0; mt < 4; mt++)
#pragma unroll
                for (int nt = 0; nt < 4; nt++)
                    MMA_TF32(acc[mt][nt], af[mt], bf[nt]);
        }

        if (it + 2 < NIT) {
            const float* ga = gA + (it + 2) * 32;
            const float* gb = gB + (it + 2) * 32;
            uint32_t o2 = (uint32_t)st2 * TG_BUFB;
#pragma unroll
            for (int i = 0; i < 4; i++) {
                CP_ASYNC16(dA + o2 + 16 * i, ga + 4 * i);
                CP_ASYNC16(dB + o2 + 16 * i, gb + 4 * i);
            }
            CP_COMMIT();
        }
        st  = (st  == 2) ? 0 : st  + 1;
        st2 = (st2 == 2) ? 0 : st2 + 1;
    }

    if (mode == 1) {
        // gate: only cols 0..7 valid (wn==0, nt==0, 2*lc<8 always true)
        if (wn == 0) {
#pragma unroll
            for (int mt = 0; mt < 4; mt++) {
                int r0 = by * 128 + wm * 64 + mt * 16 + lr;
                int c  = 2 * lc;
                if (c < NHH) {
                    g_g0[r0 * NHH + c]           = 1.f / (1.f + expf(-acc[mt][0][0]));
                    g_g0[r0 * NHH + c + 1]       = 1.f / (1.f + expf(-acc[mt][0][1]));
                    g_g0[(r0 + 8) * NHH + c]     = 1.f / (1.f + expf(-acc[mt][0][2]));
                    g_g0[(r0 + 8) * NHH + c + 1] = 1.f / (1.f + expf(-acc[mt][0][3]));
                }
            }
        }
        return;
    }

#pragma unroll
    for (int mt = 0; mt < 4; mt++) {
#pragma unroll
        for (int nt = 0; nt < 4; nt++) {
            int r = by * 128 + wm * 64 + mt * 16 + lr;
            int c = bx * 128 + wn * 32 + nt * 8 + 2 * lc;
            size_t off0 = (size_t)r * N + c;
            size_t off1 = (size_t)(r + 8) * N + c;
            float2 lo = make_float2(acc[mt][nt][0], acc[mt][nt][1]);
            float2 hi = make_float2(acc[mt][nt][2], acc[mt][nt][3]);
            if (Cadd) {
                float2 x0 = *(const float2*)(Cadd + off0);
                float2 x1 = *(const float2*)(Cadd + off1);
                lo.x += x0.x; lo.y += x0.y;
                hi.x += x1.x; hi.y += x1.y;
            }
            *(float2*)(C + off0) = lo;
            *(float2*)(C + off1) = hi;
        }
    }
}

// out-projection (standalone)
__global__ void __launch_bounds__(256, 2) tgemm_nt(
    const float* __restrict__ A, const float* __restrict__ Bm,
    const float* __restrict__ Cadd, float* __restrict__ C, int N, int K)
{
    gemm_body(A, Bm, Cadd, C, N, K, blockIdx.x, blockIdx.y, 127, 0);
}

// merged front-end: q-proj (512 blocks) + k/v-proj (256) + gate (32) + dpow (1)
__global__ void __launch_bounds__(256, 2) proj_all(
    const float* __restrict__ x,  const float* __restrict__ wq,
    const float* __restrict__ wk, const float* __restrict__ wv,
    const float* __restrict__ wg,
    float* __restrict__ qp, float* __restrict__ k0p, float* __restrict__ v0p)
{
    int bid = blockIdx.x;
    if (bid < 512) {
        gemm_body(x, wq, nullptr, qp, PROJ, DD, bid & 3, bid >> 2, 127, 0);
    } else if (bid < 768) {
        int i = bid - 512;
        int bx = i & 7, by = i >> 3;
        int sel = bx >> 2;
        gemm_body(x, sel ? wv : wk, nullptr, sel ? v0p : k0p,
                  PROJ, DD, bx & 3, by, 127, 0);
    } else if (bid < 800) {
        int by = bid - 768;                 // 0..31 over batch-0 tokens
        gemm_body(x, wg, nullptr, nullptr, NHH, DD, 0, by, 7, 1);
    } else {
        // dpow table (consumed first by chunkw, a later launch)
        if (threadIdx.x == 0) {
            double p = 1.0;
            for (int i = 0; i <= 128; i++) { g_dpow[i] = (float)p; p *= 0.95; }
        }
    }
}

// ---------------- per-chunk decayed write sum ----------------
__global__ __launch_bounds__(256) void chunkw_kernel()
{
    __shared__ float Ks[32][68];
    __shared__ float Vs[32][68];
    int h = blockIdx.x, c = blockIdx.y;
    int t = threadIdx.x, tx = t & 15, ty = t >> 4;

    float acc[4][4];
#pragma unroll
    for (int i = 0; i < 4; i++)
#pragma unroll
        for (int j = 0; j < 4; j++) acc[i][j] = 0.f;

    for (int jt = 0; jt < 4; jt++) {
#pragma unroll
        for (int pp = 0; pp < 2; pp++) {
            int p = t * 2 + pp;
            int j = p >> 4, kk4 = (p & 15) << 2;
            int row = c * CHUNK + jt * 32 + j;
            float s = g_dpow[127 - (jt * 32 + j)] * 0.1f * g_g0[row * NHH + h];
            float4 kv = *(const float4*)(g_k0 + (size_t)row * PROJ + h * 64 + kk4);
            Ks[j][kk4+0] = kv.x * s; Ks[j][kk4+1] = kv.y * s;
            Ks[j][kk4+2] = kv.z * s; Ks[j][kk4+3] = kv.w * s;
            float4 vv = *(const float4*)(g_v0 + (size_t)row * PROJ + h * 64 + kk4);
            Vs[j][kk4+0] = vv.x; Vs[j][kk4+1] = vv.y;
            Vs[j][kk4+2] = vv.z; Vs[j][kk4+3] = vv.w;
        }
        __syncthreads();
#pragma unroll
        for (int j = 0; j < 32; j++) {
            float kr[4], vr[4];
            *(float4*)kr = *(const float4*)&Ks[j][ty * 4];
            *(float4*)vr = *(const float4*)&Vs[j][tx * 4];
#pragma unroll
            for (int ii = 0; ii < 4; ii++)
#pragma unroll
                for (int jj = 0; jj < 4; jj++)
                    acc[ii][jj] += kr[ii] * vr[jj];
        }
        __syncthreads();
    }
#pragma unroll
    for (int ii = 0; ii < 4; ii++) {
        float4 o = make_float4(acc[ii][0], acc[ii][1], acc[ii][2], acc[ii][3]);
        *(float4*)(g_W + ((size_t)(c * NHH + h) * 64 + ty * 4 + ii) * 64 + tx * 4) = o;
    }
}

// ---------------- state prefix scan over chunks (MLP-unrolled x4) ----------
__global__ void scan_kernel()
{
    int e = blockIdx.x * blockDim.x + threadIdx.x;   // 0..32767
    float fw = 0.f;
    const float dc = g_dpow[128];
#pragma unroll
    for (int c = 0; c < NC; c += 4) {
        // 4 independent loads issued together (MLP=4 hides DRAM latency)
        float w0 = g_W[(size_t)(c + 0) * STATE_SZ + e];
        float w1 = g_W[(size_t)(c + 1) * STATE_SZ + e];
        float w2 = g_W[(size_t)(c + 2) * STATE_SZ + e];
        float w3 = g_W[(size_t)(c + 3) * STATE_SZ + e];
        g_Fst[(size_t)(c + 0) * STATE_SZ + e] = fw; fw = dc * fw + w0;
        g_Fst[(size_t)(c + 1) * STATE_SZ + e] = fw; fw = dc * fw + w1;
        g_Fst[(size_t)(c + 2) * STATE_SZ + e] = fw; fw = dc * fw + w2;
        g_Fst[(size_t)(c + 3) * STATE_SZ + e] = fw; fw = dc * fw + w3;
    }
}

// ================= tensor-core retrieval =================
#define RT_QP 68
#define RT_SP 36
#define RS_QS 0
#define RS_FT (RS_QS + 128 * RT_QP)
#define RS_KT (RS_FT + 64 * RT_QP)
#define RS_VT (RS_KT + 32 * RT_QP)
#define RS_AS (RS_VT + 64 * RT_SP)
#define RS_SG (RS_AS + 128 * RT_SP)
#define RT_SMEM ((RS_SG + 128) * 4)

__global__ void __launch_bounds__(256, 2) retrieve_tc()
{
    extern __shared__ float sm[];
    uint32_t sbase = (uint32_t)__cvta_generic_to_shared(sm);
    int h = blockIdx.x, c = blockIdx.y, b = blockIdx.z;
    int t = threadIdx.x;
    int warp = t >> 5, lane = t & 31;
    int wr = warp >> 1, wc = warp & 1;
    int g  = lane >> 3, gr = lane & 7;
    int lr = lane >> 2, lc = lane & 3;

    float* Qs = sm + RS_QS;
    float* Ft = sm + RS_FT;
    float* Kt = sm + RS_KT;
    float* Vt = sm + RS_VT;
    float* As = sm + RS_AS;
    float* sg = sm + RS_SG;

#pragma unroll
    for (int pp = 0; pp < 8; pp++) {
        int p = t + 256 * pp;
        int i = p >> 4, k4 = (p & 15) << 2;
        float4 v = *(const float4*)(g_q + (size_t)(b * SS + c * CHUNK + i) * PROJ + h * 64 + k4);
        Qs[i * RT_QP + k4 + 0] = v.x; Qs[i * RT_QP + k4 + 1] = v.y;
        Qs[i * RT_QP + k4 + 2] = v.z; Qs[i * RT_QP + k4 + 3] = v.w;
    }
#pragma unroll
    for (int pp = 0; pp < 4; pp++) {
        int p = t + 256 * pp;
        int k = p >> 4, v4 = (p & 15) << 2;
        float4 v = *(const float4*)(g_Fst + (size_t)c * STATE_SZ + h * 4096 + k * 64 + v4);
        Ft[(v4 + 0) * RT_QP + k] = v.x; Ft[(v4 + 1) * RT_QP + k] = v.y;
        Ft[(v4 + 2) * RT_QP + k] = v.z; Ft[(v4 + 3) * RT_QP + k] = v.w;
    }
    if (t < 128) sg[t] = 0.1f * g_g0[(c * CHUNK + t) * NHH + h];
    __syncthreads();

    uint32_t qA[2], aA[2], fB[2], vB[2], kB;
#pragma unroll
    for (int mt = 0; mt < 2; mt++) {
        qA[mt] = sbase + (uint32_t)((RS_QS + (wr * 32 + mt * 16 + (g & 1) * 8 + gr) * RT_QP
                                     + (g >> 1) * 4) * 4);
        aA[mt] = sbase + (uint32_t)((RS_AS + (wr * 32 + mt * 16 + (g & 1) * 8 + gr) * RT_SP
                                     + (g >> 1) * 4) * 4);
    }
#pragma unroll
    for (int np = 0; np < 2; np++) {
        fB[np] = sbase + (uint32_t)((RS_FT + (wc * 32 + (2 * np + (g >> 1)) * 8 + gr) * RT_QP
                                     + (g & 1) * 4) * 4);
        vB[np] = sbase + (uint32_t)((RS_VT + (wc * 32 + (2 * np + (g >> 1)) * 8 + gr) * RT_SP
                                     + (g & 1) * 4) * 4);
    }
    kB = sbase + (uint32_t)((RS_KT + (wc * 16 + (g >> 1) * 8 + gr) * RT_QP + (g & 1) * 4) * 4);

    float racc[2][4][4];
#pragma unroll
    for (int i = 0; i < 2; i++)
#pragma unroll
        for (int j = 0; j < 4; j++)
#pragma unroll
            for (int r = 0; r < 4; r++) racc[i][j][r] = 0.f;

#pragma unroll
    for (int ks = 0; ks < 8; ks++) {
        uint32_t af[2][4], bf[4][2];
#pragma unroll
        for (int mt = 0; mt < 2; mt++)
            LDSM4(af[mt][0], af[mt][1], af[mt][2], af[mt][3], qA[mt] + ks * 32);
#pragma unroll
        for (int np = 0; np < 2; np++)
            LDSM4(bf[2 * np][0], bf[2 * np][1], bf[2 * np + 1][0], bf[2 * np + 1][1],
                  fB[np] + ks * 32);
#pragma unroll
        for (int mt = 0; mt < 2; mt++)
#pragma unroll
            for (int nt = 0; nt < 4; nt++)
                MMA_TF32(racc[mt][nt], af[mt], bf[nt]);
    }
#pragma unroll
    for (int mt = 0; mt < 2; mt++) {
        int r0 = wr * 32 + mt * 16 + lr;
        float l0 = g_dpow[r0], l1 = g_dpow[r0 + 8];
#pragma unroll
        for (int nt = 0; nt < 4; nt++) {
            racc[mt][nt][0] *= l0; racc[mt][nt][1] *= l0;
            racc[mt][nt][2] *= l1; racc[mt][nt][3] *= l1;
        }
    }

    for (int jt = 0; jt < 4; jt++) {
        __syncthreads();
#pragma unroll
        for (int pp = 0; pp < 2; pp++) {
            int p = t + 256 * pp;
            int j = p >> 4, k4 = (p & 15) << 2;
            int row = c * CHUNK + jt * 32 + j;
            float4 kv = *(const float4*)(g_k0 + (size_t)row * PROJ + h * 64 + k4);
            Kt[j * RT_QP + k4 + 0] = kv.x; Kt[j * RT_QP + k4 + 1] = kv.y;
            Kt[j * RT_QP + k4 + 2] = kv.z; Kt[j * RT_QP + k4 + 3] = kv.w;
            float4 vv = *(const float4*)(g_v0 + (size_t)row * PROJ + h * 64 + k4);
            Vt[(k4 + 0) * RT_SP + j] = vv.x; Vt[(k4 + 1) * RT_SP + j] = vv.y;
            Vt[(k4 + 2) * RT_SP + j] = vv.z; Vt[(k4 + 3) * RT_SP + j] = vv.w;
        }
        __syncthreads();

        float qk[2][2][4];
#pragma unroll
        for (int i = 0; i < 2; i++)
#pragma unroll
            for (int j = 0; j < 2; j++)
#pragma unroll
                for (int r = 0; r < 4; r++) qk[i][j][r] = 0.f;
#pragma unroll
        for (int ks = 0; ks < 8; ks++) {
            uint32_t af[2][4], bf[2][2];
#pragma unroll
            for (int mt = 0; mt < 2; mt++)
                LDSM4(af[mt][0], af[mt][1], af[mt][2], af[mt][3], qA[mt] + ks * 32);
            LDSM4(bf[0][0], bf[0][1], bf[1][0], bf[1][1], kB + ks * 32);
#pragma unroll
            for (int mt = 0; mt < 2; mt++)
#pragma unroll
                for (int nt = 0; nt < 2; nt++)
                    MMA_TF32(qk[mt][nt], af[mt], bf[nt]);
        }

#pragma unroll
        for (int mt = 0; mt < 2; mt++) {
            int i0 = wr * 32 + mt * 16 + lr, i1 = i0 + 8;
#pragma unroll
            for (int nt = 0; nt < 2; nt++) {
                int jl = wc * 16 + nt * 8 + 2 * lc;
                int jg0 = jt * 32 + jl, jg1 = jg0 + 1;
                float w;
                w = (jg0 < i0) ? g_dpow[i0 - 1 - jg0] * sg[jg0] : 0.f;
                As[i0 * RT_SP + jl]     = qk[mt][nt][0] * w;
                w = (jg1 < i0) ? g_dpow[i0 - 1 - jg1] * sg[jg1] : 0.f;
                As[i0 * RT_SP + jl + 1] = qk[mt][nt][1] * w;
                w = (jg0 < i1) ? g_dpow[i1 - 1 - jg0] * sg[jg0] : 0.f;
                As[i1 * RT_SP + jl]     = qk[mt][nt][2] * w;
                w = (jg1 < i1) ? g_dpow[i1 - 1 - jg1] * sg[jg1] : 0.f;
                As[i1 * RT_SP + jl + 1] = qk[mt][nt][3] * w;
            }
        }
        __syncthreads();

#pragma unroll
        for (int ks = 0; ks < 4; ks++) {
            uint32_t af[2][4], bf[4][2];
#pragma unroll
            for (int mt = 0; mt < 2; mt++)
                LDSM4(af[mt][0], af[mt][1], af[mt][2], af[mt][3], aA[mt] + ks * 32);
#pragma unroll
            for (int np = 0; np < 2; np++)
                LDSM4(bf[2 * np][0], bf[2 * np][1], bf[2 * np + 1][0], bf[2 * np + 1][1],
                      vB[np] + ks * 32);
#pragma unroll
            for (int mt = 0; mt < 2; mt++)
#pragma unroll
                for (int nt = 0; nt < 4; nt++)
                    MMA_TF32(racc[mt][nt], af[mt], bf[nt]);
        }
    }

#pragma unroll
    for (int mt = 0; mt < 2; mt++) {
#pragma unroll
        for (int nt = 0; nt < 4; nt++) {
            int i = wr * 32 + mt * 16 + lr;
            int v = wc * 32 + nt * 8 + 2 * lc;
            size_t off0 = (size_t)(b * SS + c * CHUNK + i) * PROJ + h * 64 + v;
            size_t off1 = (size_t)(b * SS + c * CHUNK + i + 8) * PROJ + h * 64 + v;
            *(float2*)(g_retr + off0) = make_float2(racc[mt][nt][0], racc[mt][nt][1]);
            *(float2*)(g_retr + off1) = make_float2(racc[mt][nt][2], racc[mt][nt][3]);
        }
    }
}

// ---------------- host launch ----------------
extern "C" void kernel_launch(void* const* d_in, const int* in_sizes, int n_in,
                              void* d_out, int out_size)
{
    (void)in_sizes; (void)n_in; (void)out_size;
    const float* x  = (const float*)d_in[0];
    const float* wk = (const float*)d_in[1];
    const float* wv = (const float*)d_in[2];
    const float* wq = (const float*)d_in[3];
    const float* wg = (const float*)d_in[4];
    const float* wo = (const float*)d_in[5];
    float* out = (float*)d_out;

    float *qp, *k0p, *v0p, *retrp;
    cudaGetSymbolAddress((void**)&qp,    g_q);
    cudaGetSymbolAddress((void**)&k0p,   g_k0);
    cudaGetSymbolAddress((void**)&v0p,   g_v0);
    cudaGetSymbolAddress((void**)&retrp, g_retr);

    cudaFuncSetAttribute(retrieve_tc,
                         cudaFuncAttributeMaxDynamicSharedMemorySize, RT_SMEM);
    cudaFuncSetAttribute(tgemm_nt,
                         cudaFuncAttributeMaxDynamicSharedMemorySize, TG_SMEM);
    cudaFuncSetAttribute(proj_all,
                         cudaFuncAttributeMaxDynamicSharedMemorySize, TG_SMEM);

    // merged front-end: q-proj + k/v-proj + gate + dpow in one launch
    proj_all<<<801, 256, TG_SMEM>>>(x, wq, wk, wv, wg, qp, k0p, v0p);

    // chunked linear-attention decomposition of the scan
    chunkw_kernel<<<dim3(NHH, NC), 256>>>();
    scan_kernel<<<256, 128>>>();
    retrieve_tc<<<dim3(NHH, NC, BB), 256, RT_SMEM>>>();

    // out = x + retrieved @ w_out^T
    tgemm_nt<<<dim3(6, 128), 256, TG_SMEM>>>(retrp, wo, x, out, DD, PROJ);
}

// round 12
// speedup vs baseline: 1.0768x; 1.0768x over previous
#include <cuda_runtime.h>
#include <stdint.h>
#include <math.h>

// Problem constants
#define BB      4
#define SS      4096
#define DD      768
#define NHH     8
#define DKV     64
#define PROJ    512          // NH*DK = NH*DV
#define NTOK    16384        // B*S
#define CHUNK   128
#define NC      32           // S / CHUNK
#define STATE_SZ 32768       // NH*DK*DV

// ---------------- device scratch (static, no allocation) ----------------
__device__ float g_q   [NTOK * PROJ];
__device__ float g_k0  [SS * PROJ];
__device__ float g_v0  [SS * PROJ];
__device__ float g_g0  [SS * NHH];
__device__ float g_W   [NC * STATE_SZ];
__device__ float g_Fst [NC * STATE_SZ];
__device__ float g_retr[NTOK * PROJ];
__device__ float g_dpow[136];

__global__ void dpow_init_kernel() {
    if (threadIdx.x == 0 && blockIdx.x == 0) {
        double p = 1.0;
        for (int i = 0; i <= 128; i++) { g_dpow[i] = (float)p; p *= 0.95; }
    }
}

// ---------------- tensor-core plumbing (legacy mma path; tcgen05 is not
// available: harness builds compute_103 PTX which ptxas rejects for tcgen05) --
#define MMA_TF32(d, a, b)                                                     \
    asm volatile("mma.sync.aligned.m16n8k8.row.col.f32.tf32.tf32.f32 "        \
                 "{%0,%1,%2,%3}, {%4,%5,%6,%7}, {%8,%9}, {%0,%1,%2,%3};"      \
                 : "+f"((d)[0]), "+f"((d)[1]), "+f"((d)[2]), "+f"((d)[3])     \
                 : "r"((a)[0]), "r"((a)[1]), "r"((a)[2]), "r"((a)[3]),        \
                   "r"((b)[0]), "r"((b)[1]))

#define LDSM4(r0, r1, r2, r3, addr)                                           \
    asm volatile("ldmatrix.sync.aligned.m8n8.x4.shared.b16 {%0,%1,%2,%3}, [%4];" \
                 : "=r"(r0), "=r"(r1), "=r"(r2), "=r"(r3) : "r"(addr))

#define CP_ASYNC16(dst, src)                                                  \
    asm volatile("cp.async.cg.shared.global [%0], [%1], 16;" :: "r"(dst), "l"(src))
#define CP_COMMIT() asm volatile("cp.async.commit_group;")
#define CP_WAIT1()  asm volatile("cp.async.wait_group 1;")
#define CP_WAIT0()  asm volatile("cp.async.wait_group 0;")

// ================= projection GEMM body =================
// 128x128 block, BK=32, 256 threads = 8 warps (2x4), warp tile 64x32.
// 3-stage cp.async pipeline, one __syncthreads per K-iter.
// Smem row-major, pitch 36 floats (conflict-free: bank=(4r+c) mod 32).
#define TG_P      36
#define TG_BUFB   (128 * TG_P * 4)             // bytes per stage buffer (18432)
#define TG_SMEM   (6 * TG_BUFB)                // A[3] + B[3] = 110592 bytes

// mode 0: C[r][c] (+Cadd) normal store.  mode 1: gate — write sigmoid of
// cols 0..7 into g_g0[token*NHH+col]; B has only 8 valid rows (bmask=7).
__device__ __forceinline__ void gemm_body(
    const float* __restrict__ A, const float* __restrict__ Bm,
    const float* __restrict__ Cadd, float* __restrict__ C,
    int N, int K, int bx, int by, int bmask, int mode)
{
    extern __shared__ float smg[];
    uint32_t sA = (uint32_t)__cvta_generic_to_shared(smg);
    uint32_t sB = sA + 3 * TG_BUFB;

    int t    = threadIdx.x;
    int warp = t >> 5, lane = t & 31;
    int wm = warp >> 2, wn = warp & 3;     // warp grid 2 x 4
    int g  = lane >> 3, gr = lane & 7;     // ldmatrix groups
    int lr = lane >> 2, lc = lane & 3;     // mma C-fragment decomposition

    int ldr = t & 127, ldc = (t >> 7) * 16;
    const float* gA = A  + (size_t)(by * 128 + ldr) * K + ldc;
    const float* gB = Bm + (size_t)(bx * 128 + (ldr & bmask)) * K + ldc;
    uint32_t dA = sA + (uint32_t)(ldr * TG_P + ldc) * 4;
    uint32_t dB = sB + (uint32_t)(ldr * TG_P + ldc) * 4;

    uint32_t aAddr[4];
#pragma unroll
    for (int mt = 0; mt < 4; mt++)
        aAddr[mt] = sA + (uint32_t)(((wm * 64 + mt * 16 + (g & 1) * 8 + gr) * TG_P
                                     + (g >> 1) * 4) * 4);
    uint32_t bAddr[2];
#pragma unroll
    for (int np = 0; np < 2; np++)
        bAddr[np] = sB + (uint32_t)(((wn * 32 + (2 * np + (g >> 1)) * 8 + gr) * TG_P
                                     + (g & 1) * 4) * 4);

    float acc[4][4][4];
#pragma unroll
    for (int i = 0; i < 4; i++)
#pragma unroll
        for (int j = 0; j < 4; j++)
#pragma unroll
            for (int r = 0; r < 4; r++) acc[i][j][r] = 0.f;

    const int NIT = K >> 5;

    // prologue: stages 0 and 1
#pragma unroll
    for (int i = 0; i < 4; i++) {
        CP_ASYNC16(dA + 16 * i, gA + 4 * i);
        CP_ASYNC16(dB + 16 * i, gB + 4 * i);
    }
    CP_COMMIT();
#pragma unroll
    for (int i = 0; i < 4; i++) {
        CP_ASYNC16(dA + TG_BUFB + 16 * i, gA + 32 + 4 * i);
        CP_ASYNC16(dB + TG_BUFB + 16 * i, gB + 32 + 4 * i);
    }
    CP_COMMIT();

    int st = 0, st2 = 2;
    for (int it = 0; it < NIT; it++) {
        if (it < NIT - 1) CP_WAIT1(); else CP_WAIT0();
        __syncthreads();

        uint32_t oa = (uint32_t)st * TG_BUFB;
#pragma unroll
        for (int ks = 0; ks < 4; ks++) {
            uint32_t af[4][4];
#pragma unroll
            for (int mt = 0; mt < 4; mt++)
                LDSM4(af[mt][0], af[mt][1], af[mt][2], af[mt][3],
                      aAddr[mt] + oa + ks * 32);
            uint32_t bf[4][2];
#pragma unroll
            for (int np = 0; np < 2; np++)
                LDSM4(bf[2 * np][0], bf[2 * np][1], bf[2 * np + 1][0], bf[2 * np + 1][1],
                      bAddr[np] + oa + ks * 32);
#pragma unroll
            for (int mt = 0; mt < 4; mt++)
#pragma unroll
                for (int nt = 0; nt < 4; nt++)
                    MMA_TF32(acc[mt][nt], af[mt], bf[nt]);
        }

        if (it + 2 < NIT) {
            const float* ga = gA + (it + 2) * 32;
            const float* gb = gB + (it + 2) * 32;
            uint32_t o2 = (uint32_t)st2 * TG_BUFB;
#pragma unroll
            for (int i = 0; i < 4; i++) {
                CP_ASYNC16(dA + o2 + 16 * i, ga + 4 * i);
                CP_ASYNC16(dB + o2 + 16 * i, gb + 4 * i);
            }
            CP_COMMIT();
        }
        st  = (st  == 2) ? 0 : st  + 1;
        st2 = (st2 == 2) ? 0 : st2 + 1;
    }

    if (mode == 1) {
        // gate: only cols 0..7 valid (wn==0, nt==0, 2*lc<8 always true)
        if (wn == 0) {
#pragma unroll
            for (int mt = 0; mt < 4; mt++) {
                int r0 = by * 128 + wm * 64 + mt * 16 + lr;
                int c  = 2 * lc;
                if (c < NHH) {
                    g_g0[r0 * NHH + c]           = 1.f / (1.f + expf(-acc[mt][0][0]));
                    g_g0[r0 * NHH + c + 1]       = 1.f / (1.f + expf(-acc[mt][0][1]));
                    g_g0[(r0 + 8) * NHH + c]     = 1.f / (1.f + expf(-acc[mt][0][2]));
                    g_g0[(r0 + 8) * NHH + c + 1] = 1.f / (1.f + expf(-acc[mt][0][3]));
                }
            }
        }
        return;
    }

#pragma unroll
    for (int mt = 0; mt < 4; mt++) {
#pragma unroll
        for (int nt = 0; nt < 4; nt++) {
            int r = by * 128 + wm * 64 + mt * 16 + lr;
            int c = bx * 128 + wn * 32 + nt * 8 + 2 * lc;
            size_t off0 = (size_t)r * N + c;
            size_t off1 = (size_t)(r + 8) * N + c;
            float2 lo = make_float2(acc[mt][nt][0], acc[mt][nt][1]);
            float2 hi = make_float2(acc[mt][nt][2], acc[mt][nt][3]);
            if (Cadd) {
                float2 x0 = *(const float2*)(Cadd + off0);
                float2 x1 = *(const float2*)(Cadd + off1);
                lo.x += x0.x; lo.y += x0.y;
                hi.x += x1.x; hi.y += x1.y;
            }
            *(float2*)(C + off0) = lo;
            *(float2*)(C + off1) = hi;
        }
    }
}

// out-projection (standalone)
__global__ void __launch_bounds__(256, 2) tgemm_nt(
    const float* __restrict__ A, const float* __restrict__ Bm,
    const float* __restrict__ Cadd, float* __restrict__ C, int N, int K)
{
    gemm_body(A, Bm, Cadd, C, N, K, blockIdx.x, blockIdx.y, 127, 0);
}

// merged front-end: q-proj (512 blocks) + k/v-proj (256) + gate (32)
__global__ void __launch_bounds__(256, 2) proj_all(
    const float* __restrict__ x,  const float* __restrict__ wq,
    const float* __restrict__ wk, const float* __restrict__ wv,
    const float* __restrict__ wg,
    float* __restrict__ qp, float* __restrict__ k0p, float* __restrict__ v0p)
{
    int bid = blockIdx.x;
    if (bid < 512) {
        gemm_body(x, wq, nullptr, qp, PROJ, DD, bid & 3, bid >> 2, 127, 0);
    } else if (bid < 768) {
        int i = bid - 512;
        int bx = i & 7, by = i >> 3;
        int sel = bx >> 2;
        gemm_body(x, sel ? wv : wk, nullptr, sel ? v0p : k0p,
                  PROJ, DD, bx & 3, by, 127, 0);
    } else {
        int by = bid - 768;                 // 0..31 over batch-0 tokens
        gemm_body(x, wg, nullptr, nullptr, NHH, DD, 0, by, 7, 1);
    }
}

// ---------------- per-chunk decayed write sum ----------------
__global__ __launch_bounds__(256) void chunkw_kernel()
{
    __shared__ float Ks[32][68];
    __shared__ float Vs[32][68];
    int h = blockIdx.x, c = blockIdx.y;
    int t = threadIdx.x, tx = t & 15, ty = t >> 4;

    float acc[4][4];
#pragma unroll
    for (int i = 0; i < 4; i++)
#pragma unroll
        for (int j = 0; j < 4; j++) acc[i][j] = 0.f;

    for (int jt = 0; jt < 4; jt++) {
#pragma unroll
        for (int pp = 0; pp < 2; pp++) {
            int p = t * 2 + pp;
            int j = p >> 4, kk4 = (p & 15) << 2;
            int row = c * CHUNK + jt * 32 + j;
            float s = g_dpow[127 - (jt * 32 + j)] * 0.1f * g_g0[row * NHH + h];
            float4 kv = *(const float4*)(g_k0 + (size_t)row * PROJ + h * 64 + kk4);
            Ks[j][kk4+0] = kv.x * s; Ks[j][kk4+1] = kv.y * s;
            Ks[j][kk4+2] = kv.z * s; Ks[j][kk4+3] = kv.w * s;
            float4 vv = *(const float4*)(g_v0 + (size_t)row * PROJ + h * 64 + kk4);
            Vs[j][kk4+0] = vv.x; Vs[j][kk4+1] = vv.y;
            Vs[j][kk4+2] = vv.z; Vs[j][kk4+3] = vv.w;
        }
        __syncthreads();
#pragma unroll
        for (int j = 0; j < 32; j++) {
            float kr[4], vr[4];
            *(float4*)kr = *(const float4*)&Ks[j][ty * 4];
            *(float4*)vr = *(const float4*)&Vs[j][tx * 4];
#pragma unroll
            for (int ii = 0; ii < 4; ii++)
#pragma unroll
                for (int jj = 0; jj < 4; jj++)
                    acc[ii][jj] += kr[ii] * vr[jj];
        }
        __syncthreads();
    }
#pragma unroll
    for (int ii = 0; ii < 4; ii++) {
        float4 o = make_float4(acc[ii][0], acc[ii][1], acc[ii][2], acc[ii][3]);
        *(float4*)(g_W + ((size_t)(c * NHH + h) * 64 + ty * 4 + ii) * 64 + tx * 4) = o;
    }
}

// ---------------- state prefix scan over chunks (MLP-unrolled x4) ----------
__global__ void scan_kernel()
{
    int e = blockIdx.x * blockDim.x + threadIdx.x;   // 0..32767
    float fw = 0.f;
    const float dc = g_dpow[128];
#pragma unroll
    for (int c = 0; c < NC; c += 4) {
        // 4 independent loads issued together (MLP=4 hides DRAM latency)
        float w0 = g_W[(size_t)(c + 0) * STATE_SZ + e];
        float w1 = g_W[(size_t)(c + 1) * STATE_SZ + e];
        float w2 = g_W[(size_t)(c + 2) * STATE_SZ + e];
        float w3 = g_W[(size_t)(c + 3) * STATE_SZ + e];
        g_Fst[(size_t)(c + 0) * STATE_SZ + e] = fw; fw = dc * fw + w0;
        g_Fst[(size_t)(c + 1) * STATE_SZ + e] = fw; fw = dc * fw + w1;
        g_Fst[(size_t)(c + 2) * STATE_SZ + e] = fw; fw = dc * fw + w2;
        g_Fst[(size_t)(c + 3) * STATE_SZ + e] = fw; fw = dc * fw + w3;
    }
}

// ================= tensor-core retrieval =================
#define RT_QP 68
#define RT_SP 36
#define RS_QS 0
#define RS_FT (RS_QS + 128 * RT_QP)
#define RS_KT (RS_FT + 64 * RT_QP)
#define RS_VT (RS_KT + 32 * RT_QP)
#define RS_AS (RS_VT + 64 * RT_SP)
#define RS_SG (RS_AS + 128 * RT_SP)
#define RT_SMEM ((RS_SG + 128) * 4)

__global__ void __launch_bounds__(256, 2) retrieve_tc()
{
    extern __shared__ float sm[];
    uint32_t sbase = (uint32_t)__cvta_generic_to_shared(sm);
    int h = blockIdx.x, c = blockIdx.y, b = blockIdx.z;
    int t = threadIdx.x;
    int warp = t >> 5, lane = t & 31;
    int wr = warp >> 1, wc = warp & 1;
    int g  = lane >> 3, gr = lane & 7;
    int lr = lane >> 2, lc = lane & 3;

    float* Qs = sm + RS_QS;
    float* Ft = sm + RS_FT;
    float* Kt = sm + RS_KT;
    float* Vt = sm + RS_VT;
    float* As = sm + RS_AS;
    float* sg = sm + RS_SG;

#pragma unroll
    for (int pp = 0; pp < 8; pp++) {
        int p = t + 256 * pp;
        int i = p >> 4, k4 = (p & 15) << 2;
        float4 v = *(const float4*)(g_q + (size_t)(b * SS + c * CHUNK + i) * PROJ + h * 64 + k4);
        Qs[i * RT_QP + k4 + 0] = v.x; Qs[i * RT_QP + k4 + 1] = v.y;
        Qs[i * RT_QP + k4 + 2] = v.z; Qs[i * RT_QP + k4 + 3] = v.w;
    }
#pragma unroll
    for (int pp = 0; pp < 4; pp++) {
        int p = t + 256 * pp;
        int k = p >> 4, v4 = (p & 15) << 2;
        float4 v = *(const float4*)(g_Fst + (size_t)c * STATE_SZ + h * 4096 + k * 64 + v4);
        Ft[(v4 + 0) * RT_QP + k] = v.x; Ft[(v4 + 1) * RT_QP + k] = v.y;
        Ft[(v4 + 2) * RT_QP + k] = v.z; Ft[(v4 + 3) * RT_QP + k] = v.w;
    }
    if (t < 128) sg[t] = 0.1f * g_g0[(c * CHUNK + t) * NHH + h];
    __syncthreads();

    uint32_t qA[2], aA[2], fB[2], vB[2], kB;
#pragma unroll
    for (int mt = 0; mt < 2; mt++) {
        qA[mt] = sbase + (uint32_t)((RS_QS + (wr * 32 + mt * 16 + (g & 1) * 8 + gr) * RT_QP
                                     + (g >> 1) * 4) * 4);
        aA[mt] = sbase + (uint32_t)((RS_AS + (wr * 32 + mt * 16 + (g & 1) * 8 + gr) * RT_SP
                                     + (g >> 1) * 4) * 4);
    }
#pragma unroll
    for (int np = 0; np < 2; np++) {
        fB[np] = sbase + (uint32_t)((RS_FT + (wc * 32 + (2 * np + (g >> 1)) * 8 + gr) * RT_QP
                                     + (g & 1) * 4) * 4);
        vB[np] = sbase + (uint32_t)((RS_VT + (wc * 32 + (2 * np + (g >> 1)) * 8 + gr) * RT_SP
                                     + (g & 1) * 4) * 4);
    }
    kB = sbase + (uint32_t)((RS_KT + (wc * 16 + (g >> 1) * 8 + gr) * RT_QP + (g & 1) * 4) * 4);

    float racc[2][4][4];
#pragma unroll
    for (int i = 0; i < 2; i++)
#pragma unroll
        for (int j = 0; j < 4; j++)
#pragma unroll
            for (int r = 0; r < 4; r++) racc[i][j][r] = 0.f;

#pragma unroll
    for (int ks = 0; ks < 8; ks++) {
        uint32_t af[2][4], bf[4][2];
#pragma unroll
        for (int mt = 0; mt < 2; mt++)
            LDSM4(af[mt][0], af[mt][1], af[mt][2], af[mt][3], qA[mt] + ks * 32);
#pragma unroll
        for (int np = 0; np < 2; np++)
            LDSM4(bf[2 * np][0], bf[2 * np][1], bf[2 * np + 1][0], bf[2 * np + 1][1],
                  fB[np] + ks * 32);
#pragma unroll
        for (int mt = 0; mt < 2; mt++)
#pragma unroll
            for (int nt = 0; nt < 4; nt++)
                MMA_TF32(racc[mt][nt], af[mt], bf[nt]);
    }
#pragma unroll
    for (int mt = 0; mt < 2; mt++) {
        int r0 = wr * 32 + mt * 16 + lr;
        float l0 = g_dpow[r0], l1 = g_dpow[r0 + 8];
#pragma unroll
        for (int nt = 0; nt < 4; nt++) {
            racc[mt][nt][0] *= l0; racc[mt][nt][1] *= l0;
            racc[mt][nt][2] *= l1; racc[mt][nt][3] *= l1;
        }
    }

    for (int jt = 0; jt < 4; jt++) {
        __syncthreads();
#pragma unroll
        for (int pp = 0; pp < 2; pp++) {
            int p = t + 256 * pp;
            int j = p >> 4, k4 = (p & 15) << 2;
            int row = c * CHUNK + jt * 32 + j;
            float4 kv = *(const float4*)(g_k0 + (size_t)row * PROJ + h * 64 + k4);
            Kt[j * RT_QP + k4 + 0] = kv.x; Kt[j * RT_QP + k4 + 1] = kv.y;
            Kt[j * RT_QP + k4 + 2] = kv.z; Kt[j * RT_QP + k4 + 3] = kv.w;
            float4 vv = *(const float4*)(g_v0 + (size_t)row * PROJ + h * 64 + k4);
            Vt[(k4 + 0) * RT_SP + j] = vv.x; Vt[(k4 + 1) * RT_SP + j] = vv.y;
            Vt[(k4 + 2) * RT_SP + j] = vv.z; Vt[(k4 + 3) * RT_SP + j] = vv.w;
        }
        __syncthreads();

        float qk[2][2][4];
#pragma unroll
        for (int i = 0; i < 2; i++)
#pragma unroll
            for (int j = 0; j < 2; j++)
#pragma unroll
                for (int r = 0; r < 4; r++) qk[i][j][r] = 0.f;
#pragma unroll
        for (int ks = 0; ks < 8; ks++) {
            uint32_t af[2][4], bf[2][2];
#pragma unroll
            for (int mt = 0; mt < 2; mt++)
                LDSM4(af[mt][0], af[mt][1], af[mt][2], af[mt][3], qA[mt] + ks * 32);
            LDSM4(bf[0][0], bf[0][1], bf[1][0], bf[1][1], kB + ks * 32);
#pragma unroll
            for (int mt = 0; mt < 2; mt++)
#pragma unroll
                for (int nt = 0; nt < 2; nt++)
                    MMA_TF32(qk[mt][nt], af[mt], bf[nt]);
        }

#pragma unroll
        for (int mt = 0; mt < 2; mt++) {
            int i0 = wr * 32 + mt * 16 + lr, i1 = i0 + 8;
#pragma unroll
            for (int nt = 0; nt < 2; nt++) {
                int jl = wc * 16 + nt * 8 + 2 * lc;
                int jg0 = jt * 32 + jl, jg1 = jg0 + 1;
                float w;
                w = (jg0 < i0) ? g_dpow[i0 - 1 - jg0] * sg[jg0] : 0.f;
                As[i0 * RT_SP + jl]     = qk[mt][nt][0] * w;
                w = (jg1 < i0) ? g_dpow[i0 - 1 - jg1] * sg[jg1] : 0.f;
                As[i0 * RT_SP + jl + 1] = qk[mt][nt][1] * w;
                w = (jg0 < i1) ? g_dpow[i1 - 1 - jg0] * sg[jg0] : 0.f;
                As[i1 * RT_SP + jl]     = qk[mt][nt][2] * w;
                w = (jg1 < i1) ? g_dpow[i1 - 1 - jg1] * sg[jg1] : 0.f;
                As[i1 * RT_SP + jl + 1] = qk[mt][nt][3] * w;
            }
        }
        __syncthreads();

#pragma unroll
        for (int ks = 0; ks < 4; ks++) {
            uint32_t af[2][4], bf[4][2];
#pragma unroll
            for (int mt = 0; mt < 2; mt++)
                LDSM4(af[mt][0], af[mt][1], af[mt][2], af[mt][3], aA[mt] + ks * 32);
#pragma unroll
            for (int np = 0; np < 2; np++)
                LDSM4(bf[2 * np][0], bf[2 * np][1], bf[2 * np + 1][0], bf[2 * np + 1][1],
                      vB[np] + ks * 32);
#pragma unroll
            for (int mt = 0; mt < 2; mt++)
#pragma unroll
                for (int nt = 0; nt < 4; nt++)
                    MMA_TF32(racc[mt][nt], af[mt], bf[nt]);
        }
    }

#pragma unroll
    for (int mt = 0; mt < 2; mt++) {
#pragma unroll
        for (int nt = 0; nt < 4; nt++) {
            int i = wr * 32 + mt * 16 + lr;
            int v = wc * 32 + nt * 8 + 2 * lc;
            size_t off0 = (size_t)(b * SS + c * CHUNK + i) * PROJ + h * 64 + v;
            size_t off1 = (size_t)(b * SS + c * CHUNK + i + 8) * PROJ + h * 64 + v;
            *(float2*)(g_retr + off0) = make_float2(racc[mt][nt][0], racc[mt][nt][1]);
            *(float2*)(g_retr + off1) = make_float2(racc[mt][nt][2], racc[mt][nt][3]);
        }
    }
}

// ---------------- host launch ----------------
extern "C" void kernel_launch(void* const* d_in, const int* in_sizes, int n_in,
                              void* d_out, int out_size)
{
    (void)in_sizes; (void)n_in; (void)out_size;
    const float* x  = (const float*)d_in[0];
    const float* wk = (const float*)d_in[1];
    const float* wv = (const float*)d_in[2];
    const float* wq = (const float*)d_in[3];
    const float* wg = (const float*)d_in[4];
    const float* wo = (const float*)d_in[5];
    float* out = (float*)d_out;

    float *qp, *k0p, *v0p, *retrp;
    cudaGetSymbolAddress((void**)&qp,    g_q);
    cudaGetSymbolAddress((void**)&k0p,   g_k0);
    cudaGetSymbolAddress((void**)&v0p,   g_v0);
    cudaGetSymbolAddress((void**)&retrp, g_retr);

    cudaFuncSetAttribute(retrieve_tc,
                         cudaFuncAttributeMaxDynamicSharedMemorySize, RT_SMEM);
    cudaFuncSetAttribute(tgemm_nt,
                         cudaFuncAttributeMaxDynamicSharedMemorySize, TG_SMEM);
    cudaFuncSetAttribute(proj_all,
                         cudaFuncAttributeMaxDynamicSharedMemorySize, TG_SMEM);

    dpow_init_kernel<<<1, 1>>>();

    // merged front-end: q-proj + k/v-proj + gate in one 800-block launch
    proj_all<<<800, 256, TG_SMEM>>>(x, wq, wk, wv, wg, qp, k0p, v0p);

    // chunked linear-attention decomposition of the scan
    chunkw_kernel<<<dim3(NHH, NC), 256>>>();
    scan_kernel<<<128, 256>>>();
    retrieve_tc<<<dim3(NHH, NC, BB), 256, RT_SMEM>>>();

    // out = x + retrieved @ w_out^T
    tgemm_nt<<<dim3(6, 128), 256, TG_SMEM>>>(retrp, wo, x, out, DD, PROJ);
}

// round 13
// speedup vs baseline: 2.2925x; 2.1289x over previous
#include <cuda_runtime.h>
#include <cuda_fp16.h>
#include <stdint.h>
#include <math.h>

// Problem constants
#define BB      4
#define SS      4096
#define DD      768
#define NHH     8
#define PROJ    512          // NH*DK = NH*DV
#define NTOK    16384        // B*S
#define CHUNK   128
#define NC      32           // S / CHUNK
#define STATE_SZ 32768       // NH*DK*DV

// ---------------- device scratch (static, no allocation) ----------------
__device__ __half g_xh  [NTOK * DD];       // x in fp16
__device__ __half g_wkh [PROJ * DD];
__device__ __half g_wvh [PROJ * DD];
__device__ __half g_wqh [PROJ * DD];
__device__ __half g_wgh [NHH * DD];
__device__ __half g_woh [DD * PROJ];
__device__ __half g_qh  [NTOK * PROJ];     // q (all batches), fp16
__device__ __half g_k0h [SS * PROJ];       // k batch 0, fp16
__device__ __half g_v0h [SS * PROJ];       // v batch 0, fp16
__device__ __half g_retrh[NTOK * PROJ];    // retrieved, fp16
__device__ float  g_g0  [SS * NHH];
__device__ float  g_W   [NC * STATE_SZ];
__device__ float  g_Fst [NC * STATE_SZ];
__device__ float  g_dpow[136];

// ---------------- convert f32 inputs -> fp16 (+ dpow table) ----------------
#define XN  (NTOK * DD)
#define WN  (PROJ * DD)
#define GN  (NHH * DD)
#define CV_TOT4 ((XN + 3 * WN + GN + WN) / 4)

__global__ void convert_kernel(
    const float* __restrict__ x,  const float* __restrict__ wk,
    const float* __restrict__ wv, const float* __restrict__ wq,
    const float* __restrict__ wg, const float* __restrict__ wo)
{
    if (blockIdx.x == 0 && threadIdx.x == 0) {
        double p = 1.0;
        for (int i = 0; i <= 128; i++) { g_dpow[i] = (float)p; p *= 0.95; }
    }
    size_t stride = (size_t)gridDim.x * blockDim.x;
    for (size_t i = blockIdx.x * (size_t)blockDim.x + threadIdx.x;
         i < CV_TOT4; i += stride) {
        size_t e = i * 4;
        const float* src; __half* dst; size_t off;
        if      (e < XN)                    { src = x;  dst = g_xh;  off = e; }
        else if (e < XN + WN)               { src = wk; dst = g_wkh; off = e - XN; }
        else if (e < XN + 2 * WN)           { src = wv; dst = g_wvh; off = e - XN - WN; }
        else if (e < XN + 3 * WN)           { src = wq; dst = g_wqh; off = e - XN - 2 * WN; }
        else if (e < XN + 3 * WN + GN)      { src = wg; dst = g_wgh; off = e - XN - 3 * WN; }
        else                                { src = wo; dst = g_woh; off = e - XN - 3 * WN - GN; }
        float4 v = *(const float4*)(src + off);
        *(__half2*)(dst + off)     = __floats2half2_rn(v.x, v.y);
        *(__half2*)(dst + off + 2) = __floats2half2_rn(v.z, v.w);
    }
}

// ---------------- tensor-core plumbing (fp16 m16n8k16; tcgen05 unavailable:
// harness emits compute_103 PTX which ptxas rejects for tcgen05) ------------
#define MMA_F16(d, a, b)                                                      \
    asm volatile("mma.sync.aligned.m16n8k16.row.col.f32.f16.f16.f32 "         \
                 "{%0,%1,%2,%3}, {%4,%5,%6,%7}, {%8,%9}, {%0,%1,%2,%3};"      \
                 : "+f"((d)[0]), "+f"((d)[1]), "+f"((d)[2]), "+f"((d)[3])     \
                 : "r"((a)[0]), "r"((a)[1]), "r"((a)[2]), "r"((a)[3]),        \
                   "r"((b)[0]), "r"((b)[1]))

#define LDSM4(r0, r1, r2, r3, addr)                                           \
    asm volatile("ldmatrix.sync.aligned.m8n8.x4.shared.b16 {%0,%1,%2,%3}, [%4];" \
                 : "=r"(r0), "=r"(r1), "=r"(r2), "=r"(r3) : "r"(addr))

#define CP_ASYNC16(dst, src)                                                  \
    asm volatile("cp.async.cg.shared.global [%0], [%1], 16;" :: "r"(dst), "l"(src))
#define CP_COMMIT() asm volatile("cp.async.commit_group;")
#define CP_WAIT1()  asm volatile("cp.async.wait_group 1;")
#define CP_WAIT0()  asm volatile("cp.async.wait_group 0;")

// ================= fp16 projection GEMM body =================
// 128x128 block, BK=32 (64B rows), 256 threads = 8 warps (2x4), warp 64x32.
// 3-stage cp.async pipeline. Smem pitch 40 halves (80B): the eight 16B row
// segments of any 8-row group land in disjoint bank ranges.
#define TG_PB     80                           // pitch bytes
#define TG_BUFB   (128 * TG_PB)                // 10240 bytes per stage buffer
#define TG_SMEM   (6 * TG_BUFB)                // A[3] + B[3] = 61440 bytes

// mode 0: fp16 C store. mode 1: gate (sigmoid -> g_g0). mode 2: f32 C + Cadd.
__device__ __forceinline__ void gemm_body(
    const __half* __restrict__ A, const __half* __restrict__ Bm,
    const float* __restrict__ Cadd, void* __restrict__ Cout,
    int N, int K, int bx, int by, int bmask, int mode)
{
    extern __shared__ char smg[];
    uint32_t sA = (uint32_t)__cvta_generic_to_shared(smg);
    uint32_t sB = sA + 3 * TG_BUFB;

    int t    = threadIdx.x;
    int warp = t >> 5, lane = t & 31;
    int wm = warp >> 2, wn = warp & 3;     // warp grid 2 x 4
    int g  = lane >> 3, gr = lane & 7;     // ldmatrix groups
    int lr = lane >> 2, lc = lane & 3;     // mma C-fragment decomposition

    // loader: 2 chunks of 16B per matrix per thread per slab
    int r0c = t >> 2,        c0 = t & 3;           // chunk t
    int r1c = (t + 256) >> 2, c1 = (t + 256) & 3;  // chunk t+256
    const __half* gA0 = A + (size_t)(by * 128 + r0c) * K + c0 * 8;
    const __half* gA1 = A + (size_t)(by * 128 + r1c) * K + c1 * 8;
    const __half* gB0 = Bm + (size_t)(bx * 128 + (r0c & bmask)) * K + c0 * 8;
    const __half* gB1 = Bm + (size_t)(bx * 128 + (r1c & bmask)) * K + c1 * 8;
    uint32_t dA0 = sA + (uint32_t)(r0c * TG_PB + c0 * 16);
    uint32_t dA1 = sA + (uint32_t)(r1c * TG_PB + c1 * 16);
    uint32_t dB0 = sB + (uint32_t)(r0c * TG_PB + c0 * 16);
    uint32_t dB1 = sB + (uint32_t)(r1c * TG_PB + c1 * 16);

    // ldmatrix bases: A matrix g -> rows (g&1)*8+gr, k-bytes (g>>1)*16;
    // B matrix g -> n-rows (g>>1)*8+gr, k-bytes (g&1)*16 (per nt pair).
    uint32_t aAddr[4];
#pragma unroll
    for (int mt = 0; mt < 4; mt++)
        aAddr[mt] = sA + (uint32_t)((wm * 64 + mt * 16 + (g & 1) * 8 + gr) * TG_PB
                                     + (g >> 1) * 16);
    uint32_t bAddr[2];
#pragma unroll
    for (int np = 0; np < 2; np++)
        bAddr[np] = sB + (uint32_t)((wn * 32 + (2 * np + (g >> 1)) * 8 + gr) * TG_PB
                                     + (g & 1) * 16);

    float acc[4][4][4];
#pragma unroll
    for (int i = 0; i < 4; i++)
#pragma unroll
        for (int j = 0; j < 4; j++)
#pragma unroll
            for (int r = 0; r < 4; r++) acc[i][j][r] = 0.f;

    const int NIT = K >> 5;

    // prologue: stages 0 and 1
    CP_ASYNC16(dA0, gA0); CP_ASYNC16(dA1, gA1);
    CP_ASYNC16(dB0, gB0); CP_ASYNC16(dB1, gB1);
    CP_COMMIT();
    CP_ASYNC16(dA0 + TG_BUFB, gA0 + 32); CP_ASYNC16(dA1 + TG_BUFB, gA1 + 32);
    CP_ASYNC16(dB0 + TG_BUFB, gB0 + 32); CP_ASYNC16(dB1 + TG_BUFB, gB1 + 32);
    CP_COMMIT();

    int st = 0, st2 = 2;
    for (int it = 0; it < NIT; it++) {
        if (it < NIT - 1) CP_WAIT1(); else CP_WAIT0();
        __syncthreads();

        uint32_t oa = (uint32_t)st * TG_BUFB;
#pragma unroll
        for (int ks = 0; ks < 2; ks++) {           // k16 per step, 32B stride
            uint32_t af[4][4];
#pragma unroll
            for (int mt = 0; mt < 4; mt++)
                LDSM4(af[mt][0], af[mt][1], af[mt][2], af[mt][3],
                      aAddr[mt] + oa + ks * 32);
            uint32_t bf[4][2];
#pragma unroll
            for (int np = 0; np < 2; np++)
                LDSM4(bf[2 * np][0], bf[2 * np][1], bf[2 * np + 1][0], bf[2 * np + 1][1],
                      bAddr[np] + oa + ks * 32);
#pragma unroll
            for (int mt = 0; mt < 4; mt++)
#pragma unroll
                for (int nt = 0; nt < 4; nt++)
                    MMA_F16(acc[mt][nt], af[mt], bf[nt]);
        }

        if (it + 2 < NIT) {
            int ko = (it + 2) * 32;
            uint32_t o2 = (uint32_t)st2 * TG_BUFB;
            CP_ASYNC16(dA0 + o2, gA0 + ko); CP_ASYNC16(dA1 + o2, gA1 + ko);
            CP_ASYNC16(dB0 + o2, gB0 + ko); CP_ASYNC16(dB1 + o2, gB1 + ko);
            CP_COMMIT();
        }
        st  = (st  == 2) ? 0 : st  + 1;
        st2 = (st2 == 2) ? 0 : st2 + 1;
    }

    if (mode == 1) {
        if (wn == 0) {
#pragma unroll
            for (int mt = 0; mt < 4; mt++) {
                int r = by * 128 + wm * 64 + mt * 16 + lr;
                int c = 2 * lc;                     // 0..7 == head index
                g_g0[r * NHH + c]           = 1.f / (1.f + expf(-acc[mt][0][0]));
                g_g0[r * NHH + c + 1]       = 1.f / (1.f + expf(-acc[mt][0][1]));
                g_g0[(r + 8) * NHH + c]     = 1.f / (1.f + expf(-acc[mt][0][2]));
                g_g0[(r + 8) * NHH + c + 1] = 1.f / (1.f + expf(-acc[mt][0][3]));
            }
        }
        return;
    }

#pragma unroll
    for (int mt = 0; mt < 4; mt++) {
#pragma unroll
        for (int nt = 0; nt < 4; nt++) {
            int r = by * 128 + wm * 64 + mt * 16 + lr;
            int c = bx * 128 + wn * 32 + nt * 8 + 2 * lc;
            size_t off0 = (size_t)r * N + c;
            size_t off1 = (size_t)(r + 8) * N + c;
            if (mode == 0) {
                __half* Ch = (__half*)Cout;
                *(__half2*)(Ch + off0) = __floats2half2_rn(acc[mt][nt][0], acc[mt][nt][1]);
                *(__half2*)(Ch + off1) = __floats2half2_rn(acc[mt][nt][2], acc[mt][nt][3]);
            } else {
                float* Cf = (float*)Cout;
                float2 lo = make_float2(acc[mt][nt][0], acc[mt][nt][1]);
                float2 hi = make_float2(acc[mt][nt][2], acc[mt][nt][3]);
                float2 x0 = *(const float2*)(Cadd + off0);
                float2 x1 = *(const float2*)(Cadd + off1);
                lo.x += x0.x; lo.y += x0.y; hi.x += x1.x; hi.y += x1.y;
                *(float2*)(Cf + off0) = lo;
                *(float2*)(Cf + off1) = hi;
            }
        }
    }
}

// out-projection: out = x + retr @ wo^T (f32 result)
__global__ void __launch_bounds__(256, 2) tgemm_out(
    const float* __restrict__ x, float* __restrict__ out)
{
    gemm_body(g_retrh, g_woh, x, out, DD, PROJ, blockIdx.x, blockIdx.y, 127, 2);
}

// merged front-end: q-proj (512 blocks) + k/v-proj (256) + gate (32)
__global__ void __launch_bounds__(256, 2) proj_all()
{
    int bid = blockIdx.x;
    if (bid < 512) {
        gemm_body(g_xh, g_wqh, nullptr, g_qh, PROJ, DD, bid & 3, bid >> 2, 127, 0);
    } else if (bid < 768) {
        int i = bid - 512;
        int bx = i & 7, by = i >> 3;
        int sel = bx >> 2;
        gemm_body(g_xh, sel ? g_wvh : g_wkh, nullptr, sel ? g_v0h : g_k0h,
                  PROJ, DD, bx & 3, by, 127, 0);
    } else {
        gemm_body(g_xh, g_wgh, nullptr, nullptr, NHH, DD, 0, bid - 768, 7, 1);
    }
}

// ---------------- per-chunk decayed write sum ----------------
__global__ __launch_bounds__(256) void chunkw_kernel()
{
    __shared__ float Ks[32][68];
    __shared__ float Vs[32][68];
    int h = blockIdx.x, c = blockIdx.y;
    int t = threadIdx.x, tx = t & 15, ty = t >> 4;

    float acc[4][4];
#pragma unroll
    for (int i = 0; i < 4; i++)
#pragma unroll
        for (int j = 0; j < 4; j++) acc[i][j] = 0.f;

    for (int jt = 0; jt < 4; jt++) {
        {
            int j = t >> 3, kk8 = (t & 7) * 8;
            int row = c * CHUNK + jt * 32 + j;
            float s = g_dpow[127 - (jt * 32 + j)] * 0.1f * g_g0[row * NHH + h];
            union { uint4 u; __half hh[8]; } kv, vv;
            kv.u = *(const uint4*)(g_k0h + (size_t)row * PROJ + h * 64 + kk8);
            vv.u = *(const uint4*)(g_v0h + (size_t)row * PROJ + h * 64 + kk8);
#pragma unroll
            for (int q = 0; q < 8; q++) {
                Ks[j][kk8 + q] = __half2float(kv.hh[q]) * s;
                Vs[j][kk8 + q] = __half2float(vv.hh[q]);
            }
        }
        __syncthreads();
#pragma unroll
        for (int j = 0; j < 32; j++) {
            float kr[4], vr[4];
            *(float4*)kr = *(const float4*)&Ks[j][ty * 4];
            *(float4*)vr = *(const float4*)&Vs[j][tx * 4];
#pragma unroll
            for (int ii = 0; ii < 4; ii++)
#pragma unroll
                for (int jj = 0; jj < 4; jj++)
                    acc[ii][jj] += kr[ii] * vr[jj];
        }
        __syncthreads();
    }
#pragma unroll
    for (int ii = 0; ii < 4; ii++) {
        float4 o = make_float4(acc[ii][0], acc[ii][1], acc[ii][2], acc[ii][3]);
        *(float4*)(g_W + ((size_t)(c * NHH + h) * 64 + ty * 4 + ii) * 64 + tx * 4) = o;
    }
}

// ---------------- state prefix scan over chunks (MLP x4) ----------------
__global__ void scan_kernel()
{
    int e = blockIdx.x * blockDim.x + threadIdx.x;
    float fw = 0.f;
    const float dc = g_dpow[128];
#pragma unroll
    for (int c = 0; c < NC; c += 4) {
        float w0 = g_W[(size_t)(c + 0) * STATE_SZ + e];
        float w1 = g_W[(size_t)(c + 1) * STATE_SZ + e];
        float w2 = g_W[(size_t)(c + 2) * STATE_SZ + e];
        float w3 = g_W[(size_t)(c + 3) * STATE_SZ + e];
        g_Fst[(size_t)(c + 0) * STATE_SZ + e] = fw; fw = dc * fw + w0;
        g_Fst[(size_t)(c + 1) * STATE_SZ + e] = fw; fw = dc * fw + w1;
        g_Fst[(size_t)(c + 2) * STATE_SZ + e] = fw; fw = dc * fw + w2;
        g_Fst[(size_t)(c + 3) * STATE_SZ + e] = fw; fw = dc * fw + w3;
    }
}

// ================= fp16 tensor-core retrieval =================
// Pitches: 72 halves (144B, k=64 rows: Qs/Ft/Kt), 40 halves (80B, k=32: Vt/As).
#define RP64  72
#define RP32  40
#define RS_QS 0
#define RS_FT (RS_QS + 128 * 144)              // 18432
#define RS_KT (RS_FT + 64 * 144)               // 27648
#define RS_VT (RS_KT + 32 * 144)               // 32256
#define RS_AS (RS_VT + 64 * 80)                // 37376
#define RS_SG (RS_AS + 128 * 80)               // 47616
#define RT_SMEM (RS_SG + 512)                  // 48128 bytes

__global__ void __launch_bounds__(256, 2) retrieve_tc()
{
    extern __shared__ char smr[];
    uint32_t sbase = (uint32_t)__cvta_generic_to_shared(smr);
    __half* Qs = (__half*)(smr + RS_QS);
    __half* Ft = (__half*)(smr + RS_FT);
    __half* Kt = (__half*)(smr + RS_KT);
    __half* Vt = (__half*)(smr + RS_VT);
    __half* As = (__half*)(smr + RS_AS);
    float*  sg = (float*)(smr + RS_SG);

    int h = blockIdx.x, c = blockIdx.y, b = blockIdx.z;
    int t = threadIdx.x;
    int warp = t >> 5, lane = t & 31;
    int wr = warp >> 1, wc = warp & 1;         // 4 x 2 warp grid
    int g  = lane >> 3, gr = lane & 7;
    int lr = lane >> 2, lc = lane & 3;

    // load Q (128 x 64 halves)
#pragma unroll
    for (int i = 0; i < 4; i++) {
        int p = t + 256 * i;
        int row = p >> 3, c8 = (p & 7) * 8;
        *(uint4*)(Qs + row * RP64 + c8) =
            *(const uint4*)(g_qh + (size_t)(b * SS + c * CHUNK + row) * PROJ + h * 64 + c8);
    }
    // load F transposed: Ft[v][k] = F[k][v], f32 -> fp16
#pragma unroll
    for (int i = 0; i < 4; i++) {
        int p = t + 256 * i;
        int k = p >> 4, v4 = (p & 15) * 4;
        float4 v = *(const float4*)(g_Fst + (size_t)c * STATE_SZ + h * 4096 + k * 64 + v4);
        Ft[(v4 + 0) * RP64 + k] = __float2half(v.x);
        Ft[(v4 + 1) * RP64 + k] = __float2half(v.y);
        Ft[(v4 + 2) * RP64 + k] = __float2half(v.z);
        Ft[(v4 + 3) * RP64 + k] = __float2half(v.w);
    }
    if (t < 128) sg[t] = 0.1f * g_g0[(c * CHUNK + t) * NHH + h];
    __syncthreads();

    uint32_t qA[2], aA[2], fB[2], vB[2], kB;
#pragma unroll
    for (int mt = 0; mt < 2; mt++) {
        qA[mt] = sbase + (uint32_t)(RS_QS + (wr * 32 + mt * 16 + (g & 1) * 8 + gr) * 144
                                    + (g >> 1) * 16);
        aA[mt] = sbase + (uint32_t)(RS_AS + (wr * 32 + mt * 16 + (g & 1) * 8 + gr) * 80
                                    + (g >> 1) * 16);
    }
#pragma unroll
    for (int np = 0; np < 2; np++) {
        fB[np] = sbase + (uint32_t)(RS_FT + (wc * 32 + (2 * np + (g >> 1)) * 8 + gr) * 144
                                    + (g & 1) * 16);
        vB[np] = sbase + (uint32_t)(RS_VT + (wc * 32 + (2 * np + (g >> 1)) * 8 + gr) * 80
                                    + (g & 1) * 16);
    }
    kB = sbase + (uint32_t)(RS_KT + (wc * 16 + (g >> 1) * 8 + gr) * 144 + (g & 1) * 16);

    float racc[2][4][4];
#pragma unroll
    for (int i = 0; i < 2; i++)
#pragma unroll
        for (int j = 0; j < 4; j++)
#pragma unroll
            for (int r = 0; r < 4; r++) racc[i][j][r] = 0.f;

    // inter-chunk: R = Q @ F  (K=64 -> 4 k16 steps)
#pragma unroll
    for (int ks = 0; ks < 4; ks++) {
        uint32_t af[2][4], bf[4][2];
#pragma unroll
        for (int mt = 0; mt < 2; mt++)
            LDSM4(af[mt][0], af[mt][1], af[mt][2], af[mt][3], qA[mt] + ks * 32);
#pragma unroll
        for (int np = 0; np < 2; np++)
            LDSM4(bf[2 * np][0], bf[2 * np][1], bf[2 * np + 1][0], bf[2 * np + 1][1],
                  fB[np] + ks * 32);
#pragma unroll
        for (int mt = 0; mt < 2; mt++)
#pragma unroll
            for (int nt = 0; nt < 4; nt++)
                MMA_F16(racc[mt][nt], af[mt], bf[nt]);
    }
#pragma unroll
    for (int mt = 0; mt < 2; mt++) {
        int r0 = wr * 32 + mt * 16 + lr;
        float l0 = g_dpow[r0], l1 = g_dpow[r0 + 8];
#pragma unroll
        for (int nt = 0; nt < 4; nt++) {
            racc[mt][nt][0] *= l0; racc[mt][nt][1] *= l0;
            racc[mt][nt][2] *= l1; racc[mt][nt][3] *= l1;
        }
    }

    for (int jt = 0; jt < 4; jt++) {
        __syncthreads();
        {
            int j = t >> 3, kk8 = (t & 7) * 8;
            int row = c * CHUNK + jt * 32 + j;
            *(uint4*)(Kt + j * RP64 + kk8) =
                *(const uint4*)(g_k0h + (size_t)row * PROJ + h * 64 + kk8);
            union { uint4 u; __half hh[8]; } vv;
            vv.u = *(const uint4*)(g_v0h + (size_t)row * PROJ + h * 64 + kk8);
#pragma unroll
            for (int q = 0; q < 8; q++)
                Vt[(kk8 + q) * RP32 + j] = vv.hh[q];
        }
        __syncthreads();

        // A = Q @ K^T  (128 x 32, warp tile 32 x 16, K=64 -> 4 ks)
        float qk[2][2][4];
#pragma unroll
        for (int i = 0; i < 2; i++)
#pragma unroll
            for (int j = 0; j < 2; j++)
#pragma unroll
                for (int r = 0; r < 4; r++) qk[i][j][r] = 0.f;
#pragma unroll
        for (int ks = 0; ks < 4; ks++) {
            uint32_t af[2][4], bf[2][2];
#pragma unroll
            for (int mt = 0; mt < 2; mt++)
                LDSM4(af[mt][0], af[mt][1], af[mt][2], af[mt][3], qA[mt] + ks * 32);
            LDSM4(bf[0][0], bf[0][1], bf[1][0], bf[1][1], kB + ks * 32);
#pragma unroll
            for (int mt = 0; mt < 2; mt++)
#pragma unroll
                for (int nt = 0; nt < 2; nt++)
                    MMA_F16(qk[mt][nt], af[mt], bf[nt]);
        }

        // mask * decay * gate, store fp16 to As
#pragma unroll
        for (int mt = 0; mt < 2; mt++) {
            int i0 = wr * 32 + mt * 16 + lr, i1 = i0 + 8;
#pragma unroll
            for (int nt = 0; nt < 2; nt++) {
                int jl = wc * 16 + nt * 8 + 2 * lc;
                int jg0 = jt * 32 + jl, jg1 = jg0 + 1;
                float w0, w1, w2, w3;
                w0 = (jg0 < i0) ? g_dpow[i0 - 1 - jg0] * sg[jg0] : 0.f;
                w1 = (jg1 < i0) ? g_dpow[i0 - 1 - jg1] * sg[jg1] : 0.f;
                w2 = (jg0 < i1) ? g_dpow[i1 - 1 - jg0] * sg[jg0] : 0.f;
                w3 = (jg1 < i1) ? g_dpow[i1 - 1 - jg1] * sg[jg1] : 0.f;
                *(__half2*)(As + i0 * RP32 + jl) =
                    __floats2half2_rn(qk[mt][nt][0] * w0, qk[mt][nt][1] * w1);
                *(__half2*)(As + i1 * RP32 + jl) =
                    __floats2half2_rn(qk[mt][nt][2] * w2, qk[mt][nt][3] * w3);
            }
        }
        __syncthreads();

        // R += A @ V  (K=32 -> 2 ks)
#pragma unroll
        for (int ks = 0; ks < 2; ks++) {
            uint32_t af[2][4], bf[4][2];
#pragma unroll
            for (int mt = 0; mt < 2; mt++)
                LDSM4(af[mt][0], af[mt][1], af[mt][2], af[mt][3], aA[mt] + ks * 32);
#pragma unroll
            for (int np = 0; np < 2; np++)
                LDSM4(bf[2 * np][0], bf[2 * np][1], bf[2 * np + 1][0], bf[2 * np + 1][1],
                      vB[np] + ks * 32);
#pragma unroll
            for (int mt = 0; mt < 2; mt++)
#pragma unroll
                for (int nt = 0; nt < 4; nt++)
                    MMA_F16(racc[mt][nt], af[mt], bf[nt]);
        }
    }

    // store R as fp16
#pragma unroll
    for (int mt = 0; mt < 2; mt++) {
#pragma unroll
        for (int nt = 0; nt < 4; nt++) {
            int i = wr * 32 + mt * 16 + lr;
            int v = wc * 32 + nt * 8 + 2 * lc;
            size_t off0 = (size_t)(b * SS + c * CHUNK + i) * PROJ + h * 64 + v;
            size_t off1 = (size_t)(b * SS + c * CHUNK + i + 8) * PROJ + h * 64 + v;
            *(__half2*)(g_retrh + off0) = __floats2half2_rn(racc[mt][nt][0], racc[mt][nt][1]);
            *(__half2*)(g_retrh + off1) = __floats2half2_rn(racc[mt][nt][2], racc[mt][nt][3]);
        }
    }
}

// ---------------- host launch ----------------
extern "C" void kernel_launch(void* const* d_in, const int* in_sizes, int n_in,
                              void* d_out, int out_size)
{
    (void)in_sizes; (void)n_in; (void)out_size;
    const float* x  = (const float*)d_in[0];
    const float* wk = (const float*)d_in[1];
    const float* wv = (const float*)d_in[2];
    const float* wq = (const float*)d_in[3];
    const float* wg = (const float*)d_in[4];
    const float* wo = (const float*)d_in[5];
    float* out = (float*)d_out;

    cudaFuncSetAttribute(retrieve_tc,
                         cudaFuncAttributeMaxDynamicSharedMemorySize, RT_SMEM);
    cudaFuncSetAttribute(tgemm_out,
                         cudaFuncAttributeMaxDynamicSharedMemorySize, TG_SMEM);
    cudaFuncSetAttribute(proj_all,
                         cudaFuncAttributeMaxDynamicSharedMemorySize, TG_SMEM);

    // fp16 conversion of x + all weights (+ dpow table)
    convert_kernel<<<1024, 256>>>(x, wk, wv, wq, wg, wo);

    // merged front-end: q-proj + k/v-proj + gate in one launch
    proj_all<<<800, 256, TG_SMEM>>>();

    // chunked linear-attention decomposition of the scan
    chunkw_kernel<<<dim3(NHH, NC), 256>>>();
    scan_kernel<<<128, 256>>>();
    retrieve_tc<<<dim3(NHH, NC, BB), 256, RT_SMEM>>>();

    // out = x + retrieved @ w_out^T
    tgemm_out<<<dim3(6, 128), 256, TG_SMEM>>>(x, out);
}

// round 15
// speedup vs baseline: 2.3073x; 1.0064x over previous
#include <cuda_runtime.h>
#include <cuda_fp16.h>
#include <stdint.h>
#include <math.h>

// Problem constants
#define BB      4
#define SS      4096
#define DD      768
#define NHH     8
#define PROJ    512          // NH*DK = NH*DV
#define NTOK    16384        // B*S
#define CHUNK   128
#define NC      32           // S / CHUNK
#define STATE_SZ 32768       // NH*DK*DV

// ---------------- device scratch (static, no allocation) ----------------
__device__ __half g_xh  [NTOK * DD];       // x in fp16
__device__ __half g_wkh [PROJ * DD];
__device__ __half g_wvh [PROJ * DD];
__device__ __half g_wqh [PROJ * DD];
__device__ __half g_wgh [NHH * DD];
__device__ __half g_woh [DD * PROJ];
__device__ __half g_qh  [NTOK * PROJ];     // q (all batches), fp16
__device__ __half g_k0h [SS * PROJ];       // k batch 0, fp16
__device__ __half g_v0h [SS * PROJ];       // v batch 0, fp16
__device__ __half g_retrh[NTOK * PROJ];    // retrieved, fp16
__device__ float  g_g0  [SS * NHH];
__device__ float  g_W   [NC * STATE_SZ];
__device__ float  g_Fst [NC * STATE_SZ];
__device__ float  g_dpow[136];

// ---------------- convert f32 inputs -> fp16 (+ dpow table) ----------------
#define XN  (NTOK * DD)
#define WN  (PROJ * DD)
#define GN  (NHH * DD)
#define CV_TOT4 ((XN + 3 * WN + GN + WN) / 4)

__global__ void convert_kernel(
    const float* __restrict__ x,  const float* __restrict__ wk,
    const float* __restrict__ wv, const float* __restrict__ wq,
    const float* __restrict__ wg, const float* __restrict__ wo)
{
    if (blockIdx.x == 0 && threadIdx.x == 0) {
        double p = 1.0;
        for (int i = 0; i <= 128; i++) { g_dpow[i] = (float)p; p *= 0.95; }
    }
    size_t stride = (size_t)gridDim.x * blockDim.x;
    for (size_t i = blockIdx.x * (size_t)blockDim.x + threadIdx.x;
         i < CV_TOT4; i += stride) {
        size_t e = i * 4;
        const float* src; __half* dst; size_t off;
        if      (e < XN)                    { src = x;  dst = g_xh;  off = e; }
        else if (e < XN + WN)               { src = wk; dst = g_wkh; off = e - XN; }
        else if (e < XN + 2 * WN)           { src = wv; dst = g_wvh; off = e - XN - WN; }
        else if (e < XN + 3 * WN)           { src = wq; dst = g_wqh; off = e - XN - 2 * WN; }
        else if (e < XN + 3 * WN + GN)      { src = wg; dst = g_wgh; off = e - XN - 3 * WN; }
        else                                { src = wo; dst = g_woh; off = e - XN - 3 * WN - GN; }
        float4 v = *(const float4*)(src + off);
        *(__half2*)(dst + off)     = __floats2half2_rn(v.x, v.y);
        *(__half2*)(dst + off + 2) = __floats2half2_rn(v.z, v.w);
    }
}

// ---------------- tensor-core plumbing (fp16 m16n8k16; tcgen05 unavailable:
// harness emits compute_103 PTX which ptxas rejects for tcgen05) ------------
#define MMA_F16(d, a, b)                                                      \
    asm volatile("mma.sync.aligned.m16n8k16.row.col.f32.f16.f16.f32 "         \
                 "{%0,%1,%2,%3}, {%4,%5,%6,%7}, {%8,%9}, {%0,%1,%2,%3};"      \
                 : "+f"((d)[0]), "+f"((d)[1]), "+f"((d)[2]), "+f"((d)[3])     \
                 : "r"((a)[0]), "r"((a)[1]), "r"((a)[2]), "r"((a)[3]),        \
                   "r"((b)[0]), "r"((b)[1]))

#define LDSM4(r0, r1, r2, r3, addr)                                           \
    asm volatile("ldmatrix.sync.aligned.m8n8.x4.shared.b16 {%0,%1,%2,%3}, [%4];" \
                 : "=r"(r0), "=r"(r1), "=r"(r2), "=r"(r3) : "r"(addr))

#define CP_ASYNC16(dst, src)                                                  \
    asm volatile("cp.async.cg.shared.global [%0], [%1], 16;" :: "r"(dst), "l"(src))
#define CP_COMMIT() asm volatile("cp.async.commit_group;")
#define CP_WAIT2()  asm volatile("cp.async.wait_group 2;")
#define CP_WAIT0()  asm volatile("cp.async.wait_group 0;")

// ================= fp16 projection GEMM body =================
// 128x128 block, BK=32 (64B rows), 256 threads = 8 warps (2x4), warp 64x32.
// 4-stage cp.async pipeline (two slabs in flight during compute).
// Smem pitch 40 halves (80B): disjoint 16B segments per 8-row group.
#define TG_PB     80                           // pitch bytes
#define TG_BUFB   (128 * TG_PB)                // 10240 bytes per stage buffer
#define TG_SMEM   (8 * TG_BUFB)                // A[4] + B[4] = 81920 bytes

// mode 0: fp16 C store. mode 1: gate (sigmoid -> g_g0). mode 2: f32 C + Cadd.
__device__ __forceinline__ void gemm_body(
    const __half* __restrict__ A, const __half* __restrict__ Bm,
    const float* __restrict__ Cadd, void* __restrict__ Cout,
    int N, int K, int bx, int by, int bmask, int mode)
{
    extern __shared__ char smg[];
    uint32_t sA = (uint32_t)__cvta_generic_to_shared(smg);
    uint32_t sB = sA + 4 * TG_BUFB;

    int t    = threadIdx.x;
    int warp = t >> 5, lane = t & 31;
    int wm = warp >> 2, wn = warp & 3;     // warp grid 2 x 4
    int g  = lane >> 3, gr = lane & 7;     // ldmatrix groups
    int lr = lane >> 2, lc = lane & 3;     // mma C-fragment decomposition

    // loader: 2 chunks of 16B per matrix per thread per slab
    int r0c = t >> 2,        c0 = t & 3;           // chunk t
    int r1c = (t + 256) >> 2, c1 = (t + 256) & 3;  // chunk t+256
    const __half* gA0 = A + (size_t)(by * 128 + r0c) * K + c0 * 8;
    const __half* gA1 = A + (size_t)(by * 128 + r1c) * K + c1 * 8;
    const __half* gB0 = Bm + (size_t)(bx * 128 + (r0c & bmask)) * K + c0 * 8;
    const __half* gB1 = Bm + (size_t)(bx * 128 + (r1c & bmask)) * K + c1 * 8;
    uint32_t dA0 = sA + (uint32_t)(r0c * TG_PB + c0 * 16);
    uint32_t dA1 = sA + (uint32_t)(r1c * TG_PB + c1 * 16);
    uint32_t dB0 = sB + (uint32_t)(r0c * TG_PB + c0 * 16);
    uint32_t dB1 = sB + (uint32_t)(r1c * TG_PB + c1 * 16);

    uint32_t aAddr[4];
#pragma unroll
    for (int mt = 0; mt < 4; mt++)
        aAddr[mt] = sA + (uint32_t)((wm * 64 + mt * 16 + (g & 1) * 8 + gr) * TG_PB
                                     + (g >> 1) * 16);
    uint32_t bAddr[2];
#pragma unroll
    for (int np = 0; np < 2; np++)
        bAddr[np] = sB + (uint32_t)((wn * 32 + (2 * np + (g >> 1)) * 8 + gr) * TG_PB
                                     + (g & 1) * 16);

    float acc[4][4][4];
#pragma unroll
    for (int i = 0; i < 4; i++)
#pragma unroll
        for (int j = 0; j < 4; j++)
#pragma unroll
            for (int r = 0; r < 4; r++) acc[i][j][r] = 0.f;

    const int NIT = K >> 5;

    // prologue: stages 0, 1, 2
#pragma unroll
    for (int s = 0; s < 3; s++) {
        uint32_t o = (uint32_t)s * TG_BUFB;
        int ko = s * 32;
        CP_ASYNC16(dA0 + o, gA0 + ko); CP_ASYNC16(dA1 + o, gA1 + ko);
        CP_ASYNC16(dB0 + o, gB0 + ko); CP_ASYNC16(dB1 + o, gB1 + ko);
        CP_COMMIT();
    }

    int st = 0, st3 = 3;
    for (int it = 0; it < NIT; it++) {
        if (it < NIT - 1) CP_WAIT2(); else CP_WAIT0();
        __syncthreads();

        uint32_t oa = (uint32_t)st * TG_BUFB;
#pragma unroll
        for (int ks = 0; ks < 2; ks++) {           // k16 per step, 32B stride
            uint32_t af[4][4];
#pragma unroll
            for (int mt = 0; mt < 4; mt++)
                LDSM4(af[mt][0], af[mt][1], af[mt][2], af[mt][3],
                      aAddr[mt] + oa + ks * 32);
            uint32_t bf[4][2];
#pragma unroll
            for (int np = 0; np < 2; np++)
                LDSM4(bf[2 * np][0], bf[2 * np][1], bf[2 * np + 1][0], bf[2 * np + 1][1],
                      bAddr[np] + oa + ks * 32);
#pragma unroll
            for (int mt = 0; mt < 4; mt++)
#pragma unroll
                for (int nt = 0; nt < 4; nt++)
                    MMA_F16(acc[mt][nt], af[mt], bf[nt]);
        }

        if (it + 3 < NIT) {
            int ko = (it + 3) * 32;
            uint32_t o3 = (uint32_t)st3 * TG_BUFB;  // buffer consumed at it-1
            CP_ASYNC16(dA0 + o3, gA0 + ko); CP_ASYNC16(dA1 + o3, gA1 + ko);
            CP_ASYNC16(dB0 + o3, gB0 + ko); CP_ASYNC16(dB1 + o3, gB1 + ko);
            CP_COMMIT();
        }
        st  = (st  + 1) & 3;
        st3 = (st3 + 1) & 3;
    }

    if (mode == 1) {
        if (wn == 0) {
#pragma unroll
            for (int mt = 0; mt < 4; mt++) {
                int r = by * 128 + wm * 64 + mt * 16 + lr;
                int c = 2 * lc;                     // 0..7 == head index
                g_g0[r * NHH + c]           = 1.f / (1.f + expf(-acc[mt][0][0]));
                g_g0[r * NHH + c + 1]       = 1.f / (1.f + expf(-acc[mt][0][1]));
                g_g0[(r + 8) * NHH + c]     = 1.f / (1.f + expf(-acc[mt][0][2]));
                g_g0[(r + 8) * NHH + c + 1] = 1.f / (1.f + expf(-acc[mt][0][3]));
            }
        }
        return;
    }

#pragma unroll
    for (int mt = 0; mt < 4; mt++) {
#pragma unroll
        for (int nt = 0; nt < 4; nt++) {
            int r = by * 128 + wm * 64 + mt * 16 + lr;
            int c = bx * 128 + wn * 32 + nt * 8 + 2 * lc;
            size_t off0 = (size_t)r * N + c;
            size_t off1 = (size_t)(r + 8) * N + c;
            if (mode == 0) {
                __half* Ch = (__half*)Cout;
                *(__half2*)(Ch + off0) = __floats2half2_rn(acc[mt][nt][0], acc[mt][nt][1]);
                *(__half2*)(Ch + off1) = __floats2half2_rn(acc[mt][nt][2], acc[mt][nt][3]);
            } else {
                float* Cf = (float*)Cout;
                float2 lo = make_float2(acc[mt][nt][0], acc[mt][nt][1]);
                float2 hi = make_float2(acc[mt][nt][2], acc[mt][nt][3]);
                float2 x0 = *(const float2*)(Cadd + off0);
                float2 x1 = *(const float2*)(Cadd + off1);
                lo.x += x0.x; lo.y += x0.y; hi.x += x1.x; hi.y += x1.y;
                *(float2*)(Cf + off0) = lo;
                *(float2*)(Cf + off1) = hi;
            }
        }
    }
}

// out-projection: out = x + retr @ wo^T (f32 result)
__global__ void __launch_bounds__(256, 2) tgemm_out(
    const float* __restrict__ x, float* __restrict__ out)
{
    gemm_body(g_retrh, g_woh, x, out, DD, PROJ, blockIdx.x, blockIdx.y, 127, 2);
}

// merged front-end: q-proj (512 blocks) + k/v-proj (256) + gate (32)
__global__ void __launch_bounds__(256, 2) proj_all()
{
    int bid = blockIdx.x;
    if (bid < 512) {
        gemm_body(g_xh, g_wqh, nullptr, g_qh, PROJ, DD, bid & 3, bid >> 2, 127, 0);
    } else if (bid < 768) {
        int i = bid - 512;
        int bx = i & 7, by = i >> 3;
        int sel = bx >> 2;
        gemm_body(g_xh, sel ? g_wvh : g_wkh, nullptr, sel ? g_v0h : g_k0h,
                  PROJ, DD, bx & 3, by, 127, 0);
    } else {
        gemm_body(g_xh, g_wgh, nullptr, nullptr, NHH, DD, 0, bid - 768, 7, 1);
    }
}

// ---------------- per-chunk decayed write sum ----------------
__global__ __launch_bounds__(256) void chunkw_kernel()
{
    __shared__ float Ks[32][68];
    __shared__ float Vs[32][68];
    int h = blockIdx.x, c = blockIdx.y;
    int t = threadIdx.x, tx = t & 15, ty = t >> 4;

    float acc[4][4];
#pragma unroll
    for (int i = 0; i < 4; i++)
#pragma unroll
        for (int j = 0; j < 4; j++) acc[i][j] = 0.f;

    for (int jt = 0; jt < 4; jt++) {
        {
            int j = t >> 3, kk8 = (t & 7) * 8;
            int row = c * CHUNK + jt * 32 + j;
            float s = g_dpow[127 - (jt * 32 + j)] * 0.1f * g_g0[row * NHH + h];
            union { uint4 u; __half hh[8]; } kv, vv;
            kv.u = *(const uint4*)(g_k0h + (size_t)row * PROJ + h * 64 + kk8);
            vv.u = *(const uint4*)(g_v0h + (size_t)row * PROJ + h * 64 + kk8);
#pragma unroll
            for (int q = 0; q < 8; q++) {
                Ks[j][kk8 + q] = __half2float(kv.hh[q]) * s;
                Vs[j][kk8 + q] = __half2float(vv.hh[q]);
            }
        }
        __syncthreads();
#pragma unroll
        for (int j = 0; j < 32; j++) {
            float kr[4], vr[4];
            *(float4*)kr = *(const float4*)&Ks[j][ty * 4];
            *(float4*)vr = *(const float4*)&Vs[j][tx * 4];
#pragma unroll
            for (int ii = 0; ii < 4; ii++)
#pragma unroll
                for (int jj = 0; jj < 4; jj++)
                    acc[ii][jj] += kr[ii] * vr[jj];
        }
        __syncthreads();
    }
#pragma unroll
    for (int ii = 0; ii < 4; ii++) {
        float4 o = make_float4(acc[ii][0], acc[ii][1], acc[ii][2], acc[ii][3]);
        *(float4*)(g_W + ((size_t)(c * NHH + h) * 64 + ty * 4 + ii) * 64 + tx * 4) = o;
    }
}

// ---------------- state prefix scan over chunks (MLP x8) ----------------
__global__ void scan_kernel()
{
    int e = blockIdx.x * blockDim.x + threadIdx.x;
    float fw = 0.f;
    const float dc = g_dpow[128];
#pragma unroll
    for (int c = 0; c < NC; c += 8) {
        float w[8];
#pragma unroll
        for (int u = 0; u < 8; u++)
            w[u] = g_W[(size_t)(c + u) * STATE_SZ + e];
#pragma unroll
        for (int u = 0; u < 8; u++) {
            g_Fst[(size_t)(c + u) * STATE_SZ + e] = fw;
            fw = dc * fw + w[u];
        }
    }
}

// ================= fp16 tensor-core retrieval =================
// Pitches: 72 halves (144B, k=64 rows: Qs/Ft/Kt), 40 halves (80B, k=32: Vt/As).
#define RP64  72
#define RP32  40
#define RS_QS 0
#define RS_FT (RS_QS + 128 * 144)              // 18432
#define RS_KT (RS_FT + 64 * 144)               // 27648
#define RS_VT (RS_KT + 32 * 144)               // 32256
#define RS_AS (RS_VT + 64 * 80)                // 37376
#define RS_SG (RS_AS + 128 * 80)               // 47616
#define RT_SMEM (RS_SG + 512)                  // 48128 bytes

__global__ void __launch_bounds__(256, 2) retrieve_tc()
{
    extern __shared__ char smr[];
    uint32_t sbase = (uint32_t)__cvta_generic_to_shared(smr);
    __half* Qs = (__half*)(smr + RS_QS);
    __half* Ft = (__half*)(smr + RS_FT);
    __half* Kt = (__half*)(smr + RS_KT);
    __half* Vt = (__half*)(smr + RS_VT);
    __half* As = (__half*)(smr + RS_AS);
    float*  sg = (float*)(smr + RS_SG);

    int h = blockIdx.x, c = blockIdx.y, b = blockIdx.z;
    int t = threadIdx.x;
    int warp = t >> 5, lane = t & 31;
    int wr = warp >> 1, wc = warp & 1;         // 4 x 2 warp grid
    int g  = lane >> 3, gr = lane & 7;
    int lr = lane >> 2, lc = lane & 3;

    // load Q (128 x 64 halves)
#pragma unroll
    for (int i = 0; i < 4; i++) {
        int p = t + 256 * i;
        int row = p >> 3, c8 = (p & 7) * 8;
        *(uint4*)(Qs + row * RP64 + c8) =
            *(const uint4*)(g_qh + (size_t)(b * SS + c * CHUNK + row) * PROJ + h * 64 + c8);
    }
    // load F transposed: Ft[v][k] = F[k][v], f32 -> fp16
#pragma unroll
    for (int i = 0; i < 4; i++) {
        int p = t + 256 * i;
        int k = p >> 4, v4 = (p & 15) * 4;
        float4 v = *(const float4*)(g_Fst + (size_t)c * STATE_SZ + h * 4096 + k * 64 + v4);
        Ft[(v4 + 0) * RP64 + k] = __float2half(v.x);
        Ft[(v4 + 1) * RP64 + k] = __float2half(v.y);
        Ft[(v4 + 2) * RP64 + k] = __float2half(v.z);
        Ft[(v4 + 3) * RP64 + k] = __float2half(v.w);
    }
    if (t < 128) sg[t] = 0.1f * g_g0[(c * CHUNK + t) * NHH + h];
    __syncthreads();

    uint32_t qA[2], aA[2], fB[2], vB[2], kB;
#pragma unroll
    for (int mt = 0; mt < 2; mt++) {
        qA[mt] = sbase + (uint32_t)(RS_QS + (wr * 32 + mt * 16 + (g & 1) * 8 + gr) * 144
                                    + (g >> 1) * 16);
        aA[mt] = sbase + (uint32_t)(RS_AS + (wr * 32 + mt * 16 + (g & 1) * 8 + gr) * 80
                                    + (g >> 1) * 16);
    }
#pragma unroll
    for (int np = 0; np < 2; np++) {
        fB[np] = sbase + (uint32_t)(RS_FT + (wc * 32 + (2 * np + (g >> 1)) * 8 + gr) * 144
                                    + (g & 1) * 16);
        vB[np] = sbase + (uint32_t)(RS_VT + (wc * 32 + (2 * np + (g >> 1)) * 8 + gr) * 80
                                    + (g & 1) * 16);
    }
    kB = sbase + (uint32_t)(RS_KT + (wc * 16 + (g >> 1) * 8 + gr) * 144 + (g & 1) * 16);

    float racc[2][4][4];
#pragma unroll
    for (int i = 0; i < 2; i++)
#pragma unroll
        for (int j = 0; j < 4; j++)
#pragma unroll
            for (int r = 0; r < 4; r++) racc[i][j][r] = 0.f;

    // inter-chunk: R = Q @ F  (K=64 -> 4 k16 steps)
#pragma unroll
    for (int ks = 0; ks < 4; ks++) {
        uint32_t af[2][4], bf[4][2];
#pragma unroll
        for (int mt = 0; mt < 2; mt++)
            LDSM4(af[mt][0], af[mt][1], af[mt][2], af[mt][3], qA[mt] + ks * 32);
#pragma unroll
        for (int np = 0; np < 2; np++)
            LDSM4(bf[2 * np][0], bf[2 * np][1], bf[2 * np + 1][0], bf[2 * np + 1][1],
                  fB[np] + ks * 32);
#pragma unroll
        for (int mt = 0; mt < 2; mt++)
#pragma unroll
            for (int nt = 0; nt < 4; nt++)
                MMA_F16(racc[mt][nt], af[mt], bf[nt]);
    }
#pragma unroll
    for (int mt = 0; mt < 2; mt++) {
        int r0 = wr * 32 + mt * 16 + lr;
        float l0 = g_dpow[r0], l1 = g_dpow[r0 + 8];
#pragma unroll
        for (int nt = 0; nt < 4; nt++) {
            racc[mt][nt][0] *= l0; racc[mt][nt][1] *= l0;
            racc[mt][nt][2] *= l1; racc[mt][nt][3] *= l1;
        }
    }

    for (int jt = 0; jt < 4; jt++) {
        __syncthreads();
        {
            int j = t >> 3, kk8 = (t & 7) * 8;
            int row = c * CHUNK + jt * 32 + j;
            *(uint4*)(Kt + j * RP64 + kk8) =
                *(const uint4*)(g_k0h + (size_t)row * PROJ + h * 64 + kk8);
            union { uint4 u; __half hh[8]; } vv;
            vv.u = *(const uint4*)(g_v0h + (size_t)row * PROJ + h * 64 + kk8);
#pragma unroll
            for (int q = 0; q < 8; q++)
                Vt[(kk8 + q) * RP32 + j] = vv.hh[q];
        }
        __syncthreads();

        // A = Q @ K^T  (128 x 32, warp tile 32 x 16, K=64 -> 4 ks)
        float qk[2][2][4];
#pragma unroll
        for (int i = 0; i < 2; i++)
#pragma unroll
            for (int j = 0; j < 2; j++)
#pragma unroll
                for (int r = 0; r < 4; r++) qk[i][j][r] = 0.f;
#pragma unroll
        for (int ks = 0; ks < 4; ks++) {
            uint32_t af[2][4], bf[2][2];
#pragma unroll
            for (int mt = 0; mt < 2; mt++)
                LDSM4(af[mt][0], af[mt][1], af[mt][2], af[mt][3], qA[mt] + ks * 32);
            LDSM4(bf[0][0], bf[0][1], bf[1][0], bf[1][1], kB + ks * 32);
#pragma unroll
            for (int mt = 0; mt < 2; mt++)
#pragma unroll
                for (int nt = 0; nt < 2; nt++)
                    MMA_F16(qk[mt][nt], af[mt], bf[nt]);
        }

        // mask * decay * gate, store fp16 to As
#pragma unroll
        for (int mt = 0; mt < 2; mt++) {
            int i0 = wr * 32 + mt * 16 + lr, i1 = i0 + 8;
#pragma unroll
            for (int nt = 0; nt < 2; nt++) {
                int jl = wc * 16 + nt * 8 + 2 * lc;
                int jg0 = jt * 32 + jl, jg1 = jg0 + 1;
                float w0, w1, w2, w3;
                w0 = (jg0 < i0) ? g_dpow[i0 - 1 - jg0] * sg[jg0] : 0.f;
                w1 = (jg1 < i0) ? g_dpow[i0 - 1 - jg1] * sg[jg1] : 0.f;
                w2 = (jg0 < i1) ? g_dpow[i1 - 1 - jg0] * sg[jg0] : 0.f;
                w3 = (jg1 < i1) ? g_dpow[i1 - 1 - jg1] * sg[jg1] : 0.f;
                *(__half2*)(As + i0 * RP32 + jl) =
                    __floats2half2_rn(qk[mt][nt][0] * w0, qk[mt][nt][1] * w1);
                *(__half2*)(As + i1 * RP32 + jl) =
                    __floats2half2_rn(qk[mt][nt][2] * w2, qk[mt][nt][3] * w3);
            }
        }
        __syncthreads();

        // R += A @ V  (K=32 -> 2 ks)
#pragma unroll
        for (int ks = 0; ks < 2; ks++) {
            uint32_t af[2][4], bf[4][2];
#pragma unroll
            for (int mt = 0; mt < 2; mt++)
                LDSM4(af[mt][0], af[mt][1], af[mt][2], af[mt][3], aA[mt] + ks * 32);
#pragma unroll
            for (int np = 0; np < 2; np++)
                LDSM4(bf[2 * np][0], bf[2 * np][1], bf[2 * np + 1][0], bf[2 * np + 1][1],
                      vB[np] + ks * 32);
#pragma unroll
            for (int mt = 0; mt < 2; mt++)
#pragma unroll
                for (int nt = 0; nt < 4; nt++)
                    MMA_F16(racc[mt][nt], af[mt], bf[nt]);
        }
    }

    // store R as fp16
#pragma unroll
    for (int mt = 0; mt < 2; mt++) {
#pragma unroll
        for (int nt = 0; nt < 4; nt++) {
            int i = wr * 32 + mt * 16 + lr;
            int v = wc * 32 + nt * 8 + 2 * lc;
            size_t off0 = (size_t)(b * SS + c * CHUNK + i) * PROJ + h * 64 + v;
            size_t off1 = (size_t)(b * SS + c * CHUNK + i + 8) * PROJ + h * 64 + v;
            *(__half2*)(g_retrh + off0) = __floats2half2_rn(racc[mt][nt][0], racc[mt][nt][1]);
            *(__half2*)(g_retrh + off1) = __floats2half2_rn(racc[mt][nt][2], racc[mt][nt][3]);
        }
    }
}

// ---------------- host launch ----------------
extern "C" void kernel_launch(void* const* d_in, const int* in_sizes, int n_in,
                              void* d_out, int out_size)
{
    (void)in_sizes; (void)n_in; (void)out_size;
    const float* x  = (const float*)d_in[0];
    const float* wk = (const float*)d_in[1];
    const float* wv = (const float*)d_in[2];
    const float* wq = (const float*)d_in[3];
    const float* wg = (const float*)d_in[4];
    const float* wo = (const float*)d_in[5];
    float* out = (float*)d_out;

    cudaFuncSetAttribute(retrieve_tc,
                         cudaFuncAttributeMaxDynamicSharedMemorySize, RT_SMEM);
    cudaFuncSetAttribute(tgemm_out,
                         cudaFuncAttributeMaxDynamicSharedMemorySize, TG_SMEM);
    cudaFuncSetAttribute(proj_all,
                         cudaFuncAttributeMaxDynamicSharedMemorySize, TG_SMEM);

    // fp16 conversion of x + all weights (+ dpow table)
    convert_kernel<<<1024, 256>>>(x, wk, wv, wq, wg, wo);

    // merged front-end: q-proj + k/v-proj + gate in one launch
    proj_all<<<800, 256, TG_SMEM>>>();

    // chunked linear-attention decomposition of the scan
    chunkw_kernel<<<dim3(NHH, NC), 256>>>();
    scan_kernel<<<128, 256>>>();
    retrieve_tc<<<dim3(NHH, NC, BB), 256, RT_SMEM>>>();

    // out = x + retrieved @ w_out^T
    tgemm_out<<<dim3(6, 128), 256, TG_SMEM>>>(x, out);
}

// round 16
// speedup vs baseline: 2.3378x; 1.0132x over previous
#include <cuda_runtime.h>
#include <cuda_fp16.h>
#include <stdint.h>
#include <math.h>

// Problem constants
#define BB      4
#define SS      4096
#define DD      768
#define NHH     8
#define PROJ    512          // NH*DK = NH*DV
#define NTOK    16384        // B*S
#define CHUNK   128
#define NC      32           // S / CHUNK
#define STATE_SZ 32768       // NH*DK*DV

// ---------------- device scratch (static, no allocation) ----------------
__device__ __half g_xh  [NTOK * DD];       // x in fp16
__device__ __half g_wkh [PROJ * DD];
__device__ __half g_wvh [PROJ * DD];
__device__ __half g_wqh [PROJ * DD];
__device__ __half g_wgh [NHH * DD];
__device__ __half g_woh [DD * PROJ];
__device__ __half g_qh  [NTOK * PROJ];     // q (all batches), fp16
__device__ __half g_k0h [SS * PROJ];       // k batch 0, fp16
__device__ __half g_v0h [SS * PROJ];       // v batch 0, fp16
__device__ __half g_retrh[NTOK * PROJ];    // retrieved, fp16
__device__ float  g_g0  [SS * NHH];
__device__ float  g_W   [NC * STATE_SZ];
__device__ float  g_Fst [NC * STATE_SZ];
__device__ float  g_dpow[136];

// ---------------- convert f32 inputs -> fp16 (+ dpow table) ----------------
#define XN  (NTOK * DD)
#define WN  (PROJ * DD)
#define GN  (NHH * DD)
#define CV_TOT4 ((XN + 3 * WN + GN + WN) / 4)

__global__ void convert_kernel(
    const float* __restrict__ x,  const float* __restrict__ wk,
    const float* __restrict__ wv, const float* __restrict__ wq,
    const float* __restrict__ wg, const float* __restrict__ wo)
{
    if (blockIdx.x == 0 && threadIdx.x == 0) {
        double p = 1.0;
        for (int i = 0; i <= 128; i++) { g_dpow[i] = (float)p; p *= 0.95; }
    }
    size_t stride = (size_t)gridDim.x * blockDim.x;
    for (size_t i = blockIdx.x * (size_t)blockDim.x + threadIdx.x;
         i < CV_TOT4; i += stride) {
        size_t e = i * 4;
        const float* src; __half* dst; size_t off;
        if      (e < XN)                    { src = x;  dst = g_xh;  off = e; }
        else if (e < XN + WN)               { src = wk; dst = g_wkh; off = e - XN; }
        else if (e < XN + 2 * WN)           { src = wv; dst = g_wvh; off = e - XN - WN; }
        else if (e < XN + 3 * WN)           { src = wq; dst = g_wqh; off = e - XN - 2 * WN; }
        else if (e < XN + 3 * WN + GN)      { src = wg; dst = g_wgh; off = e - XN - 3 * WN; }
        else                                { src = wo; dst = g_woh; off = e - XN - 3 * WN - GN; }
        float4 v = *(const float4*)(src + off);
        *(__half2*)(dst + off)     = __floats2half2_rn(v.x, v.y);
        *(__half2*)(dst + off + 2) = __floats2half2_rn(v.z, v.w);
    }
}

// ---------------- tensor-core plumbing (fp16 m16n8k16; tcgen05 unavailable:
// harness emits compute_103 PTX which ptxas rejects for tcgen05) ------------
#define MMA_F16(d, a, b)                                                      \
    asm volatile("mma.sync.aligned.m16n8k16.row.col.f32.f16.f16.f32 "         \
                 "{%0,%1,%2,%3}, {%4,%5,%6,%7}, {%8,%9}, {%0,%1,%2,%3};"      \
                 : "+f"((d)[0]), "+f"((d)[1]), "+f"((d)[2]), "+f"((d)[3])     \
                 : "r"((a)[0]), "r"((a)[1]), "r"((a)[2]), "r"((a)[3]),        \
                   "r"((b)[0]), "r"((b)[1]))

#define LDSM4(r0, r1, r2, r3, addr)                                           \
    asm volatile("ldmatrix.sync.aligned.m8n8.x4.shared.b16 {%0,%1,%2,%3}, [%4];" \
                 : "=r"(r0), "=r"(r1), "=r"(r2), "=r"(r3) : "r"(addr))

#define CP_ASYNC16(dst, src)                                                  \
    asm volatile("cp.async.cg.shared.global [%0], [%1], 16;" :: "r"(dst), "l"(src))
#define CP_COMMIT() asm volatile("cp.async.commit_group;")
#define CP_WAIT1()  asm volatile("cp.async.wait_group 1;")
#define CP_WAIT0()  asm volatile("cp.async.wait_group 0;")

// ================= fp16 projection GEMM body =================
// 128x128 block, BK=32 (64B rows), 256 threads = 8 warps (2x4), warp 64x32.
// 3-stage cp.async pipeline (wait_group 1 guarantees group `it` complete at
// iter it for ALL it <= NIT-2; wait0 at the last iter). Deeper pipelines
// proved neutral AND the 4-stage wait arithmetic raced at it=NIT-2.
#define TG_PB     80                           // pitch bytes
#define TG_BUFB   (128 * TG_PB)                // 10240 bytes per stage buffer
#define TG_SMEM   (6 * TG_BUFB)                // A[3] + B[3] = 61440 bytes

// mode 0: fp16 C store. mode 1: gate (sigmoid -> g_g0). mode 2: f32 C + Cadd.
__device__ __forceinline__ void gemm_body(
    const __half* __restrict__ A, const __half* __restrict__ Bm,
    const float* __restrict__ Cadd, void* __restrict__ Cout,
    int N, int K, int bx, int by, int bmask, int mode)
{
    extern __shared__ char smg[];
    uint32_t sA = (uint32_t)__cvta_generic_to_shared(smg);
    uint32_t sB = sA + 3 * TG_BUFB;

    int t    = threadIdx.x;
    int warp = t >> 5, lane = t & 31;
    int wm = warp >> 2, wn = warp & 3;     // warp grid 2 x 4
    int g  = lane >> 3, gr = lane & 7;     // ldmatrix groups
    int lr = lane >> 2, lc = lane & 3;     // mma C-fragment decomposition

    // loader: 2 chunks of 16B per matrix per thread per slab
    int r0c = t >> 2,        c0 = t & 3;           // chunk t
    int r1c = (t + 256) >> 2, c1 = (t + 256) & 3;  // chunk t+256
    const __half* gA0 = A + (size_t)(by * 128 + r0c) * K + c0 * 8;
    const __half* gA1 = A + (size_t)(by * 128 + r1c) * K + c1 * 8;
    const __half* gB0 = Bm + (size_t)(bx * 128 + (r0c & bmask)) * K + c0 * 8;
    const __half* gB1 = Bm + (size_t)(bx * 128 + (r1c & bmask)) * K + c1 * 8;
    uint32_t dA0 = sA + (uint32_t)(r0c * TG_PB + c0 * 16);
    uint32_t dA1 = sA + (uint32_t)(r1c * TG_PB + c1 * 16);
    uint32_t dB0 = sB + (uint32_t)(r0c * TG_PB + c0 * 16);
    uint32_t dB1 = sB + (uint32_t)(r1c * TG_PB + c1 * 16);

    uint32_t aAddr[4];
#pragma unroll
    for (int mt = 0; mt < 4; mt++)
        aAddr[mt] = sA + (uint32_t)((wm * 64 + mt * 16 + (g & 1) * 8 + gr) * TG_PB
                                     + (g >> 1) * 16);
    uint32_t bAddr[2];
#pragma unroll
    for (int np = 0; np < 2; np++)
        bAddr[np] = sB + (uint32_t)((wn * 32 + (2 * np + (g >> 1)) * 8 + gr) * TG_PB
                                     + (g & 1) * 16);

    float acc[4][4][4];
#pragma unroll
    for (int i = 0; i < 4; i++)
#pragma unroll
        for (int j = 0; j < 4; j++)
#pragma unroll
            for (int r = 0; r < 4; r++) acc[i][j][r] = 0.f;

    const int NIT = K >> 5;

    // prologue: stages 0 and 1
    CP_ASYNC16(dA0, gA0); CP_ASYNC16(dA1, gA1);
    CP_ASYNC16(dB0, gB0); CP_ASYNC16(dB1, gB1);
    CP_COMMIT();
    CP_ASYNC16(dA0 + TG_BUFB, gA0 + 32); CP_ASYNC16(dA1 + TG_BUFB, gA1 + 32);
    CP_ASYNC16(dB0 + TG_BUFB, gB0 + 32); CP_ASYNC16(dB1 + TG_BUFB, gB1 + 32);
    CP_COMMIT();

    int st = 0, st2 = 2;
    for (int it = 0; it < NIT; it++) {
        if (it < NIT - 1) CP_WAIT1(); else CP_WAIT0();
        __syncthreads();

        uint32_t oa = (uint32_t)st * TG_BUFB;
#pragma unroll
        for (int ks = 0; ks < 2; ks++) {           // k16 per step, 32B stride
            uint32_t af[4][4];
#pragma unroll
            for (int mt = 0; mt < 4; mt++)
                LDSM4(af[mt][0], af[mt][1], af[mt][2], af[mt][3],
                      aAddr[mt] + oa + ks * 32);
            uint32_t bf[4][2];
#pragma unroll
            for (int np = 0; np < 2; np++)
                LDSM4(bf[2 * np][0], bf[2 * np][1], bf[2 * np + 1][0], bf[2 * np + 1][1],
                      bAddr[np] + oa + ks * 32);
#pragma unroll
            for (int mt = 0; mt < 4; mt++)
#pragma unroll
                for (int nt = 0; nt < 4; nt++)
                    MMA_F16(acc[mt][nt], af[mt], bf[nt]);
        }

        if (it + 2 < NIT) {
            int ko = (it + 2) * 32;
            uint32_t o2 = (uint32_t)st2 * TG_BUFB;
            CP_ASYNC16(dA0 + o2, gA0 + ko); CP_ASYNC16(dA1 + o2, gA1 + ko);
            CP_ASYNC16(dB0 + o2, gB0 + ko); CP_ASYNC16(dB1 + o2, gB1 + ko);
            CP_COMMIT();
        }
        st  = (st  == 2) ? 0 : st  + 1;
        st2 = (st2 == 2) ? 0 : st2 + 1;
    }

    if (mode == 1) {
        if (wn == 0) {
#pragma unroll
            for (int mt = 0; mt < 4; mt++) {
                int r = by * 128 + wm * 64 + mt * 16 + lr;
                int c = 2 * lc;                     // 0..7 == head index
                g_g0[r * NHH + c]           = 1.f / (1.f + expf(-acc[mt][0][0]));
                g_g0[r * NHH + c + 1]       = 1.f / (1.f + expf(-acc[mt][0][1]));
                g_g0[(r + 8) * NHH + c]     = 1.f / (1.f + expf(-acc[mt][0][2]));
                g_g0[(r + 8) * NHH + c + 1] = 1.f / (1.f + expf(-acc[mt][0][3]));
            }
        }
        return;
    }

#pragma unroll
    for (int mt = 0; mt < 4; mt++) {
#pragma unroll
        for (int nt = 0; nt < 4; nt++) {
            int r = by * 128 + wm * 64 + mt * 16 + lr;
            int c = bx * 128 + wn * 32 + nt * 8 + 2 * lc;
            size_t off0 = (size_t)r * N + c;
            size_t off1 = (size_t)(r + 8) * N + c;
            if (mode == 0) {
                __half* Ch = (__half*)Cout;
                *(__half2*)(Ch + off0) = __floats2half2_rn(acc[mt][nt][0], acc[mt][nt][1]);
                *(__half2*)(Ch + off1) = __floats2half2_rn(acc[mt][nt][2], acc[mt][nt][3]);
            } else {
                float* Cf = (float*)Cout;
                float2 lo = make_float2(acc[mt][nt][0], acc[mt][nt][1]);
                float2 hi = make_float2(acc[mt][nt][2], acc[mt][nt][3]);
                float2 x0 = *(const float2*)(Cadd + off0);
                float2 x1 = *(const float2*)(Cadd + off1);
                lo.x += x0.x; lo.y += x0.y; hi.x += x1.x; hi.y += x1.y;
                *(float2*)(Cf + off0) = lo;
                *(float2*)(Cf + off1) = hi;
            }
        }
    }
}

// out-projection: out = x + retr @ wo^T (f32 result)
__global__ void __launch_bounds__(256, 2) tgemm_out(
    const float* __restrict__ x, float* __restrict__ out)
{
    gemm_body(g_retrh, g_woh, x, out, DD, PROJ, blockIdx.x, blockIdx.y, 127, 2);
}

// merged front-end: q-proj (512 blocks) + k/v-proj (256) + gate (32)
__global__ void __launch_bounds__(256, 2) proj_all()
{
    int bid = blockIdx.x;
    if (bid < 512) {
        gemm_body(g_xh, g_wqh, nullptr, g_qh, PROJ, DD, bid & 3, bid >> 2, 127, 0);
    } else if (bid < 768) {
        int i = bid - 512;
        int bx = i & 7, by = i >> 3;
        int sel = bx >> 2;
        gemm_body(g_xh, sel ? g_wvh : g_wkh, nullptr, sel ? g_v0h : g_k0h,
                  PROJ, DD, bx & 3, by, 127, 0);
    } else {
        gemm_body(g_xh, g_wgh, nullptr, nullptr, NHH, DD, 0, bid - 768, 7, 1);
    }
}

// ---------------- per-chunk decayed write sum ----------------
__global__ __launch_bounds__(256) void chunkw_kernel()
{
    __shared__ float Ks[32][68];
    __shared__ float Vs[32][68];
    int h = blockIdx.x, c = blockIdx.y;
    int t = threadIdx.x, tx = t & 15, ty = t >> 4;

    float acc[4][4];
#pragma unroll
    for (int i = 0; i < 4; i++)
#pragma unroll
        for (int j = 0; j < 4; j++) acc[i][j] = 0.f;

    for (int jt = 0; jt < 4; jt++) {
        {
            int j = t >> 3, kk8 = (t & 7) * 8;
            int row = c * CHUNK + jt * 32 + j;
            float s = g_dpow[127 - (jt * 32 + j)] * 0.1f * g_g0[row * NHH + h];
            union { uint4 u; __half hh[8]; } kv, vv;
            kv.u = *(const uint4*)(g_k0h + (size_t)row * PROJ + h * 64 + kk8);
            vv.u = *(const uint4*)(g_v0h + (size_t)row * PROJ + h * 64 + kk8);
#pragma unroll
            for (int q = 0; q < 8; q++) {
                Ks[j][kk8 + q] = __half2float(kv.hh[q]) * s;
                Vs[j][kk8 + q] = __half2float(vv.hh[q]);
            }
        }
        __syncthreads();
#pragma unroll
        for (int j = 0; j < 32; j++) {
            float kr[4], vr[4];
            *(float4*)kr = *(const float4*)&Ks[j][ty * 4];
            *(float4*)vr = *(const float4*)&Vs[j][tx * 4];
#pragma unroll
            for (int ii = 0; ii < 4; ii++)
#pragma unroll
                for (int jj = 0; jj < 4; jj++)
                    acc[ii][jj] += kr[ii] * vr[jj];
        }
        __syncthreads();
    }
#pragma unroll
    for (int ii = 0; ii < 4; ii++) {
        float4 o = make_float4(acc[ii][0], acc[ii][1], acc[ii][2], acc[ii][3]);
        *(float4*)(g_W + ((size_t)(c * NHH + h) * 64 + ty * 4 + ii) * 64 + tx * 4) = o;
    }
}

// ---------------- state prefix scan over chunks (MLP x8) ----------------
__global__ void scan_kernel()
{
    int e = blockIdx.x * blockDim.x + threadIdx.x;
    float fw = 0.f;
    const float dc = g_dpow[128];
#pragma unroll
    for (int c = 0; c < NC; c += 8) {
        float w[8];
#pragma unroll
        for (int u = 0; u < 8; u++)
            w[u] = g_W[(size_t)(c + u) * STATE_SZ + e];
#pragma unroll
        for (int u = 0; u < 8; u++) {
            g_Fst[(size_t)(c + u) * STATE_SZ + e] = fw;
            fw = dc * fw + w[u];
        }
    }
}

// ================= fp16 tensor-core retrieval =================
// Full K/V chunk preloaded once; masked-A double buffered -> ONE sync per jt.
// Pitches (bytes): 144 (Qs/Ft/Kt, 64-half rows), 272 (Vt, 128-half rows),
// 80 (As). All pitches == 16 mod 128 -> ldmatrix conflict-free.
#define RP64  72                               // halves
#define VPH   136                              // halves (272B)
#define APH   40                               // halves (80B)
#define RS_QS 0
#define RS_FT (RS_QS + 128 * 144)              // 18432
#define RS_KT (RS_FT + 64 * 144)               // 27648
#define RS_VT (RS_KT + 128 * 144)              // 46080
#define RS_AS (RS_VT + 64 * 272)               // 63488
#define AS_BUFB (128 * 80)                     // 10240 per buffer
#define RS_SG (RS_AS + 2 * AS_BUFB)            // 83968
#define RT_SMEM (RS_SG + 512)                  // 84480 bytes

__global__ void __launch_bounds__(256, 2) retrieve_tc()
{
    extern __shared__ char smr[];
    uint32_t sbase = (uint32_t)__cvta_generic_to_shared(smr);
    __half* Qs = (__half*)(smr + RS_QS);
    __half* Ft = (__half*)(smr + RS_FT);
    __half* Kt = (__half*)(smr + RS_KT);
    __half* Vt = (__half*)(smr + RS_VT);
    __half* As = (__half*)(smr + RS_AS);
    float*  sg = (float*)(smr + RS_SG);

    int h = blockIdx.x, c = blockIdx.y, b = blockIdx.z;
    int t = threadIdx.x;
    int warp = t >> 5, lane = t & 31;
    int wr = warp >> 1, wc = warp & 1;         // 4 x 2 warp grid
    int g  = lane >> 3, gr = lane & 7;
    int lr = lane >> 2, lc = lane & 3;

    // ---- preload everything, one sync ----
    // Q (128 x 64 halves)
#pragma unroll
    for (int i = 0; i < 4; i++) {
        int p = t + 256 * i;
        int row = p >> 3, c8 = (p & 7) * 8;
        *(uint4*)(Qs + row * RP64 + c8) =
            *(const uint4*)(g_qh + (size_t)(b * SS + c * CHUNK + row) * PROJ + h * 64 + c8);
    }
    // F transposed: Ft[v][k] = F[k][v], f32 -> fp16
#pragma unroll
    for (int i = 0; i < 4; i++) {
        int p = t + 256 * i;
        int k = p >> 4, v4 = (p & 15) * 4;
        float4 v = *(const float4*)(g_Fst + (size_t)c * STATE_SZ + h * 4096 + k * 64 + v4);
        Ft[(v4 + 0) * RP64 + k] = __float2half(v.x);
        Ft[(v4 + 1) * RP64 + k] = __float2half(v.y);
        Ft[(v4 + 2) * RP64 + k] = __float2half(v.z);
        Ft[(v4 + 3) * RP64 + k] = __float2half(v.w);
    }
    // full K chunk (128 x 64 halves) straight
#pragma unroll
    for (int i = 0; i < 4; i++) {
        int p = t + 256 * i;
        int row = p >> 3, c8 = (p & 7) * 8;
        *(uint4*)(Kt + row * RP64 + c8) =
            *(const uint4*)(g_k0h + (size_t)(c * CHUNK + row) * PROJ + h * 64 + c8);
    }
    // full V chunk transposed: Vt[v][j] (64 rows x 128 halves)
#pragma unroll
    for (int i = 0; i < 4; i++) {
        int p = t + 256 * i;
        int j = p >> 3, kk8 = (p & 7) * 8;
        union { uint4 u; __half hh[8]; } vv;
        vv.u = *(const uint4*)(g_v0h + (size_t)(c * CHUNK + j) * PROJ + h * 64 + kk8);
#pragma unroll
        for (int q = 0; q < 8; q++)
            Vt[(kk8 + q) * VPH + j] = vv.hh[q];
    }
    if (t < 128) sg[t] = 0.1f * g_g0[(c * CHUNK + t) * NHH + h];
    __syncthreads();

    // ldmatrix bases
    uint32_t qA[2], aA[2], fB[2], vB[2], kB;
#pragma unroll
    for (int mt = 0; mt < 2; mt++) {
        qA[mt] = sbase + (uint32_t)(RS_QS + (wr * 32 + mt * 16 + (g & 1) * 8 + gr) * 144
                                    + (g >> 1) * 16);
        aA[mt] = sbase + (uint32_t)(RS_AS + (wr * 32 + mt * 16 + (g & 1) * 8 + gr) * 80
                                    + (g >> 1) * 16);
    }
#pragma unroll
    for (int np = 0; np < 2; np++) {
        fB[np] = sbase + (uint32_t)(RS_FT + (wc * 32 + (2 * np + (g >> 1)) * 8 + gr) * 144
                                    + (g & 1) * 16);
        vB[np] = sbase + (uint32_t)(RS_VT + (wc * 32 + (2 * np + (g >> 1)) * 8 + gr) * 272
                                    + (g & 1) * 16);
    }
    kB = sbase + (uint32_t)(RS_KT + (wc * 16 + (g >> 1) * 8 + gr) * 144 + (g & 1) * 16);

    float racc[2][4][4];
#pragma unroll
    for (int i = 0; i < 2; i++)
#pragma unroll
        for (int j = 0; j < 4; j++)
#pragma unroll
            for (int r = 0; r < 4; r++) racc[i][j][r] = 0.f;

    // inter-chunk: R = Q @ F  (K=64 -> 4 k16 steps)
#pragma unroll
    for (int ks = 0; ks < 4; ks++) {
        uint32_t af[2][4], bf[4][2];
#pragma unroll
        for (int mt = 0; mt < 2; mt++)
            LDSM4(af[mt][0], af[mt][1], af[mt][2], af[mt][3], qA[mt] + ks * 32);
#pragma unroll
        for (int np = 0; np < 2; np++)
            LDSM4(bf[2 * np][0], bf[2 * np][1], bf[2 * np + 1][0], bf[2 * np + 1][1],
                  fB[np] + ks * 32);
#pragma unroll
        for (int mt = 0; mt < 2; mt++)
#pragma unroll
            for (int nt = 0; nt < 4; nt++)
                MMA_F16(racc[mt][nt], af[mt], bf[nt]);
    }
#pragma unroll
    for (int mt = 0; mt < 2; mt++) {
        int r0 = wr * 32 + mt * 16 + lr;
        float l0 = g_dpow[r0], l1 = g_dpow[r0 + 8];
#pragma unroll
        for (int nt = 0; nt < 4; nt++) {
            racc[mt][nt][0] *= l0; racc[mt][nt][1] *= l0;
            racc[mt][nt][2] *= l1; racc[mt][nt][3] *= l1;
        }
    }

    // intra-chunk: 4 key-tiles of 32; one __syncthreads per tile.
    // Sync at tile jt sits between the As[b] store and the A@V read; the sync
    // at jt+1 proves all AV(jt) reads done before As[b] is rewritten at jt+2.
    for (int jt = 0; jt < 4; jt++) {
        uint32_t asOff = (uint32_t)(jt & 1) * AS_BUFB;

        // A = Q @ K^T  (128 x 32, warp tile 32 x 16, K=64 -> 4 ks)
        float qk[2][2][4];
#pragma unroll
        for (int i = 0; i < 2; i++)
#pragma unroll
            for (int j = 0; j < 2; j++)
#pragma unroll
                for (int r = 0; r < 4; r++) qk[i][j][r] = 0.f;
        uint32_t kOff = (uint32_t)jt * (32 * 144);
#pragma unroll
        for (int ks = 0; ks < 4; ks++) {
            uint32_t af[2][4], bf[2][2];
#pragma unroll
            for (int mt = 0; mt < 2; mt++)
                LDSM4(af[mt][0], af[mt][1], af[mt][2], af[mt][3], qA[mt] + ks * 32);
            LDSM4(bf[0][0], bf[0][1], bf[1][0], bf[1][1], kB + kOff + ks * 32);
#pragma unroll
            for (int mt = 0; mt < 2; mt++)
#pragma unroll
                for (int nt = 0; nt < 2; nt++)
                    MMA_F16(qk[mt][nt], af[mt], bf[nt]);
        }

        // mask * decay * gate, store fp16 to As[jt&1]
        __half* Asb = (__half*)((char*)As + asOff);
#pragma unroll
        for (int mt = 0; mt < 2; mt++) {
            int i0 = wr * 32 + mt * 16 + lr, i1 = i0 + 8;
#pragma unroll
            for (int nt = 0; nt < 2; nt++) {
                int jl = wc * 16 + nt * 8 + 2 * lc;
                int jg0 = jt * 32 + jl, jg1 = jg0 + 1;
                float w0, w1, w2, w3;
                w0 = (jg0 < i0) ? g_dpow[i0 - 1 - jg0] * sg[jg0] : 0.f;
                w1 = (jg1 < i0) ? g_dpow[i0 - 1 - jg1] * sg[jg1] : 0.f;
                w2 = (jg0 < i1) ? g_dpow[i1 - 1 - jg0] * sg[jg0] : 0.f;
                w3 = (jg1 < i1) ? g_dpow[i1 - 1 - jg1] * sg[jg1] : 0.f;
                *(__half2*)(Asb + i0 * APH + jl) =
                    __floats2half2_rn(qk[mt][nt][0] * w0, qk[mt][nt][1] * w1);
                *(__half2*)(Asb + i1 * APH + jl) =
                    __floats2half2_rn(qk[mt][nt][2] * w2, qk[mt][nt][3] * w3);
            }
        }
        __syncthreads();

        // R += A @ V  (K=32 -> 2 ks); V j-offset = jt*64 bytes within rows
        uint32_t vOff = (uint32_t)jt * 64;
#pragma unroll
        for (int ks = 0; ks < 2; ks++) {
            uint32_t af[2][4], bf[4][2];
#pragma unroll
            for (int mt = 0; mt < 2; mt++)
                LDSM4(af[mt][0], af[mt][1], af[mt][2], af[mt][3],
                      aA[mt] + asOff + ks * 32);
#pragma unroll
            for (int np = 0; np < 2; np++)
                LDSM4(bf[2 * np][0], bf[2 * np][1], bf[2 * np + 1][0], bf[2 * np + 1][1],
                      vB[np] + vOff + ks * 32);
#pragma unroll
            for (int mt = 0; mt < 2; mt++)
#pragma unroll
                for (int nt = 0; nt < 4; nt++)
                    MMA_F16(racc[mt][nt], af[mt], bf[nt]);
        }
    }

    // store R as fp16
#pragma unroll
    for (int mt = 0; mt < 2; mt++) {
#pragma unroll
        for (int nt = 0; nt < 4; nt++) {
            int i = wr * 32 + mt * 16 + lr;
            int v = wc * 32 + nt * 8 + 2 * lc;
            size_t off0 = (size_t)(b * SS + c * CHUNK + i) * PROJ + h * 64 + v;
            size_t off1 = (size_t)(b * SS + c * CHUNK + i + 8) * PROJ + h * 64 + v;
            *(__half2*)(g_retrh + off0) = __floats2half2_rn(racc[mt][nt][0], racc[mt][nt][1]);
            *(__half2*)(g_retrh + off1) = __floats2half2_rn(racc[mt][nt][2], racc[mt][nt][3]);
        }
    }
}

// ---------------- host launch ----------------
extern "C" void kernel_launch(void* const* d_in, const int* in_sizes, int n_in,
                              void* d_out, int out_size)
{
    (void)in_sizes; (void)n_in; (void)out_size;
    const float* x  = (const float*)d_in[0];
    const float* wk = (const float*)d_in[1];
    const float* wv = (const float*)d_in[2];
    const float* wq = (const float*)d_in[3];
    const float* wg = (const float*)d_in[4];
    const float* wo = (const float*)d_in[5];
    float* out = (float*)d_out;

    cudaFuncSetAttribute(retrieve_tc,
                         cudaFuncAttributeMaxDynamicSharedMemorySize, RT_SMEM);
    cudaFuncSetAttribute(tgemm_out,
                         cudaFuncAttributeMaxDynamicSharedMemorySize, TG_SMEM);
    cudaFuncSetAttribute(proj_all,
                         cudaFuncAttributeMaxDynamicSharedMemorySize, TG_SMEM);

    // fp16 conversion of x + all weights (+ dpow table)
    convert_kernel<<<1024, 256>>>(x, wk, wv, wq, wg, wo);

    // merged front-end: q-proj + k/v-proj + gate in one launch
    proj_all<<<800, 256, TG_SMEM>>>();

    // chunked linear-attention decomposition of the scan
    chunkw_kernel<<<dim3(NHH, NC), 256>>>();
    scan_kernel<<<128, 256>>>();
    retrieve_tc<<<dim3(NHH, NC, BB), 256, RT_SMEM>>>();

    // out = x + retrieved @ w_out^T
    tgemm_out<<<dim3(6, 128), 256, TG_SMEM>>>(x, out);
}